// round 2
// baseline (speedup 1.0000x reference)
#include <cuda_runtime.h>
#include <cstdint>

#define Nn   100000
#define Ee   1600000
#define Dd   64
#define HIDv 512
#define C3   192          // 3 * 64 concatenated propagated features
#define NBLK1 ((Nn + 255) / 256)   // 391
#define STATS_BLOCKS 148

// ---------------- device scratch (no allocation allowed) ----------------
__device__ __align__(16) float g_ua[Nn * Dd];
__device__ __align__(16) float g_ub[Nn * Dd];
__device__ __align__(16) float g_H[(size_t)Nn * C3];
__device__ float g_norm[Nn];
__device__ float g_norm2[Nn];
__device__ int   g_deg[Nn];
__device__ int   g_rowptr[Nn + 1];
__device__ int   g_cursor[Nn];
__device__ int   g_csr[Ee];
__device__ int   g_bsum[512];
__device__ __align__(16) float g_G[HIDv * C3];
__device__ float g_bterm[HIDv];
__device__ __align__(16) float g_Cpart[STATS_BLOCKS * C3 * C3];
__device__ float g_mHpart[STATS_BLOCKS * C3];
__device__ __align__(16) float g_Cmat[C3 * C3];
__device__ float g_mH[C3];
__device__ float g_scale[HIDv];
__device__ float g_shift[HIDv];
__device__ __align__(16) float g_W2[C3 * Dd];   // [c][o] layout
__device__ __align__(16) float g_c0[Dd];

// ---------------- graph preprocessing ----------------
__global__ void zero_deg() {
    int i = blockIdx.x * blockDim.x + threadIdx.x;
    if (i < Nn) g_deg[i] = 0;
}

__global__ void count_deg(const int* __restrict__ dst) {
    int e = blockIdx.x * blockDim.x + threadIdx.x;
    if (e < Ee) atomicAdd(&g_deg[dst[e]], 1);
}

// block-local exclusive scan of deg -> rowptr(local), block sums -> g_bsum
__global__ void scan1() {
    __shared__ int sh[256];
    int b = blockIdx.x, t = threadIdx.x;
    int i = b * 256 + t;
    int v = (i < Nn) ? g_deg[i] : 0;
    sh[t] = v;
    __syncthreads();
    for (int off = 1; off < 256; off <<= 1) {
        int x = (t >= off) ? sh[t - off] : 0;
        __syncthreads();
        sh[t] += x;
        __syncthreads();
    }
    if (i < Nn) g_rowptr[i] = sh[t] - v;   // exclusive within block
    if (t == 255) g_bsum[b] = sh[255];
}

__global__ void scan2() {
    __shared__ int sh[512];
    int t = threadIdx.x;
    int v = (t < NBLK1) ? g_bsum[t] : 0;
    sh[t] = v;
    __syncthreads();
    for (int off = 1; off < 512; off <<= 1) {
        int x = (t >= off) ? sh[t - off] : 0;
        __syncthreads();
        sh[t] += x;
        __syncthreads();
    }
    if (t < NBLK1) g_bsum[t] = sh[t] - v;  // exclusive
}

// finalize rowptr, init cursor, compute norm / norm^2
__global__ void scan3() {
    int i = blockIdx.x * 256 + threadIdx.x;
    if (i < Nn) {
        int r = g_rowptr[i] + g_bsum[blockIdx.x];
        g_rowptr[i] = r;
        g_cursor[i] = r;
        int d = g_deg[i];
        float f = (d < 1) ? 1.0f : (float)d;
        float nm = rsqrtf(f);
        g_norm[i] = nm;
        g_norm2[i] = nm * nm;
        if (i == Nn - 1) g_rowptr[Nn] = Ee;
    }
}

__global__ void csr_fill(const int* __restrict__ src, const int* __restrict__ dst) {
    int e = blockIdx.x * blockDim.x + threadIdx.x;
    if (e < Ee) {
        int d = dst[e];
        int p = atomicAdd(&g_cursor[d], 1);
        g_csr[p] = src[e];
    }
}

// u0 = norm * feats (row scaling), vectorized float4
__global__ void scale_feats(const float* __restrict__ feats) {
    int idx = blockIdx.x * blockDim.x + threadIdx.x;
    if (idx < Nn * 16) {
        int node = idx >> 4;
        float4 v = ((const float4*)feats)[idx];
        float nm = g_norm[node];
        v.x *= nm; v.y *= nm; v.z *= nm; v.w *= nm;
        ((float4*)g_ua)[idx] = v;
    }
}

// ---------------- SpMM: pull aggregation, warp per dst node ----------------
// h_{j+1} = norm .* (A u_j);  u_{j+1} = norm^2 .* (A u_j)
__global__ __launch_bounds__(256) void spmm(int srcbuf, int jcol, int writeU) {
    int node = blockIdx.x * 8 + (threadIdx.x >> 5);
    if (node >= Nn) return;
    int lane = threadIdx.x & 31;
    const float2* uin = (const float2*)(srcbuf ? g_ub : g_ua);
    float2* uout = (float2*)(srcbuf ? g_ua : g_ub);
    int beg = g_rowptr[node];
    int end = g_rowptr[node + 1];
    float ax = 0.f, ay = 0.f;
    int i = beg;
    for (; i + 4 <= end; i += 4) {
        int s0 = g_csr[i], s1 = g_csr[i + 1], s2 = g_csr[i + 2], s3 = g_csr[i + 3];
        float2 v0 = uin[s0 * 32 + lane];
        float2 v1 = uin[s1 * 32 + lane];
        float2 v2 = uin[s2 * 32 + lane];
        float2 v3 = uin[s3 * 32 + lane];
        ax += (v0.x + v1.x) + (v2.x + v3.x);
        ay += (v0.y + v1.y) + (v2.y + v3.y);
    }
    for (; i < end; i++) {
        float2 v = uin[g_csr[i] * 32 + lane];
        ax += v.x; ay += v.y;
    }
    float nm = g_norm[node];
    float2 h; h.x = ax * nm; h.y = ay * nm;
    ((float2*)g_H)[(size_t)node * 96 + jcol * 32 + lane] = h;
    if (writeU) {
        float n2 = g_norm2[node];
        float2 u; u.x = ax * n2; u.y = ay * n2;
        uout[node * 32 + lane] = u;
    }
}

// ---------------- G = blockwise fc_W @ W_j  (512 x 192) ----------------
__global__ __launch_bounds__(192) void gmat(const float* __restrict__ fcW,
                                            const float* __restrict__ w0,
                                            const float* __restrict__ w1,
                                            const float* __restrict__ w2) {
    __shared__ float fw[1536];
    int h = blockIdx.x;
    int t = threadIdx.x;
    for (int i = t; i < 1536; i += 192) fw[i] = fcW[h * 1536 + i];
    __syncthreads();
    int j = t >> 6, d = t & 63;
    const float* W = (j == 0) ? w0 : (j == 1) ? w1 : w2;
    const float* fwj = fw + j * 512;
    float acc = 0.f;
#pragma unroll 8
    for (int m = 0; m < 512; m++) acc = fmaf(fwj[m], W[m * 64 + d], acc);
    g_G[h * C3 + t] = acc;
}

// bterm[h] = fc_b[h] + fc_W[h,:] . concat(b0,b1,b2)
__global__ void bterm_kernel(const float* __restrict__ fcW, const float* __restrict__ fcb,
                             const float* __restrict__ b0, const float* __restrict__ b1,
                             const float* __restrict__ b2) {
    int h = blockIdx.x * blockDim.x + threadIdx.x;
    if (h >= HIDv) return;
    float acc = fcb[h];
    const float* row = fcW + (size_t)h * 1536;
    for (int m = 0; m < 512; m++)
        acc += row[m] * b0[m] + row[512 + m] * b1[m] + row[1024 + m] * b2[m];
    g_bterm[h] = acc;
}

// ---------------- stats: C = H^T H (raw 2nd moment), mH = colsum ----------------
__global__ __launch_bounds__(256, 1) void stats_kernel() {
    __shared__ __align__(16) float sh[64 * C3];   // 48 KB
    int tid = threadIdx.x;
    int tx = tid & 15, ty = tid >> 4;
    float acc[12][12];
#pragma unroll
    for (int a = 0; a < 12; a++)
#pragma unroll
        for (int b = 0; b < 12; b++) acc[a][b] = 0.f;
    float accm[12];
#pragma unroll
    for (int a = 0; a < 12; a++) accm[a] = 0.f;

    int ntiles = (Nn + 63) / 64;
    for (int tile = blockIdx.x; tile < ntiles; tile += gridDim.x) {
        int r0 = tile * 64;
        int nr = min(64, Nn - r0);
        __syncthreads();
        const float4* src4 = (const float4*)(g_H + (size_t)r0 * C3);
        float4* dst4 = (float4*)sh;
        int n4 = nr * (C3 / 4);
        for (int i = tid; i < n4; i += 256) dst4[i] = src4[i];
        __syncthreads();
        for (int r = 0; r < nr; r++) {
            const float* row = sh + r * C3;
            float va[12], vb[12];
#pragma unroll
            for (int a = 0; a < 12; a++) va[a] = row[tx * 12 + a];
#pragma unroll
            for (int b = 0; b < 12; b++) vb[b] = row[ty * 12 + b];
#pragma unroll
            for (int a = 0; a < 12; a++)
#pragma unroll
                for (int b = 0; b < 12; b++) acc[a][b] = fmaf(va[a], vb[b], acc[a][b]);
            if (ty == 0) {
#pragma unroll
                for (int a = 0; a < 12; a++) accm[a] += va[a];
            }
        }
    }
    float* cp = g_Cpart + (size_t)blockIdx.x * (C3 * C3);
#pragma unroll
    for (int a = 0; a < 12; a++)
        for (int b = 0; b < 12; b++)
            cp[(tx * 12 + a) * C3 + (ty * 12 + b)] = acc[a][b];
    if (ty == 0)
        for (int a = 0; a < 12; a++) g_mHpart[blockIdx.x * C3 + tx * 12 + a] = accm[a];
}

__global__ void reduce_stats() {
    int i = blockIdx.x * 256 + threadIdx.x;
    const float invN = 1.0f / (float)Nn;
    if (i < C3 * C3) {
        float s = 0.f;
        for (int p = 0; p < STATS_BLOCKS; p++) s += g_Cpart[(size_t)p * (C3 * C3) + i];
        g_Cmat[i] = s * invN;
    }
    if (i < C3) {
        float s = 0.f;
        for (int p = 0; p < STATS_BLOCKS; p++) s += g_mHpart[p * C3 + i];
        g_mH[i] = s * invN;
    }
}

// per output-feature h: mu, var via quadratic form with C; -> scale, shift
__global__ __launch_bounds__(192) void bnprep(const float* __restrict__ gamma,
                                              const float* __restrict__ beta) {
    int h = blockIdx.x, c = threadIdx.x;
    __shared__ float gsh[C3];
    __shared__ float red[C3], red2[C3];
    gsh[c] = g_G[h * C3 + c];
    __syncthreads();
    float t = 0.f;
    for (int cc = 0; cc < C3; cc++)            // C symmetric: read column c coalesced
        t = fmaf(g_Cmat[cc * C3 + c], gsh[cc], t);
    red[c]  = gsh[c] * t;                      // contributes to G^T C G
    red2[c] = gsh[c] * g_mH[c];                // contributes to G . mH
    __syncthreads();
    if (c < 64) {
        red[c]  += red[c + 64]  + red[c + 128];
        red2[c] += red2[c + 64] + red2[c + 128];
    }
    __syncthreads();
    for (int s = 32; s > 0; s >>= 1) {
        if (c < s) { red[c] += red[c + s]; red2[c] += red2[c + s]; }
        __syncthreads();
    }
    if (c == 0) {
        float quad = red[0], dot1 = red2[0], b = g_bterm[h];
        float mu  = dot1 + b;
        float ef2 = quad + 2.f * b * dot1 + b * b;
        float var = ef2 - mu * mu;
        float sc  = rsqrtf(var + 1e-5f) * gamma[h];
        g_scale[h] = sc;
        g_shift[h] = beta[h] - mu * sc;
    }
}

// fold BN scale + q into 64x192 output matrix and bias
__global__ void w2c0(const float* __restrict__ q) {
    int idx = blockIdx.x * blockDim.x + threadIdx.x;
    if (idx < C3 * Dd) {
        int o = idx & 63, c = idx >> 6;
        float s = 0.f;
#pragma unroll
        for (int k = 0; k < 8; k++) {
            int h = k * 64 + o;
            s += q[k] * g_scale[h] * g_G[h * C3 + c];
        }
        g_W2[c * Dd + o] = s;
    }
    if (idx < Dd) {
        float s = 0.f;
#pragma unroll
        for (int k = 0; k < 8; k++) {
            int h = k * 64 + idx;
            s += q[k] * (g_scale[h] * g_bterm[h] + g_shift[h]);
        }
        g_c0[idx] = s;
    }
}

// ---------------- out = H (Nx192) @ W2^T (64x192) + c0 ----------------
__global__ __launch_bounds__(256) void out_kernel(float* __restrict__ out) {
    __shared__ __align__(16) float Hs[64 * 49];
    __shared__ __align__(16) float W2s[48 * 64];
    int tid = threadIdx.x;
    int tx = tid >> 4;   // row group 0..15
    int ty = tid & 15;   // col group 0..15
    int r0 = blockIdx.x * 64;
    int nr = min(64, Nn - r0);
    float acc[4][4];
#pragma unroll
    for (int a = 0; a < 4; a++)
#pragma unroll
        for (int b = 0; b < 4; b++) acc[a][b] = 0.f;

    for (int chunk = 0; chunk < 4; chunk++) {
        int k0 = chunk * 48;
        for (int idx = tid; idx < 64 * 48; idx += 256) {
            int r = idx / 48, kk = idx % 48;
            float v = (r < nr) ? g_H[(size_t)(r0 + r) * C3 + k0 + kk] : 0.f;
            Hs[r * 49 + kk] = v;
        }
        for (int idx = tid; idx < 48 * 64; idx += 256)
            W2s[idx] = g_W2[(k0 + (idx >> 6)) * Dd + (idx & 63)];
        __syncthreads();
#pragma unroll 4
        for (int kk = 0; kk < 48; kk++) {
            float va[4];
#pragma unroll
            for (int a = 0; a < 4; a++) va[a] = Hs[(tx * 4 + a) * 49 + kk];
            float4 v4 = *(const float4*)&W2s[kk * 64 + ty * 4];
#pragma unroll
            for (int a = 0; a < 4; a++) {
                acc[a][0] = fmaf(va[a], v4.x, acc[a][0]);
                acc[a][1] = fmaf(va[a], v4.y, acc[a][1]);
                acc[a][2] = fmaf(va[a], v4.z, acc[a][2]);
                acc[a][3] = fmaf(va[a], v4.w, acc[a][3]);
            }
        }
        __syncthreads();
    }
    float4 cc = *(const float4*)&g_c0[ty * 4];
#pragma unroll
    for (int a = 0; a < 4; a++) {
        int r = r0 + tx * 4 + a;
        if (r < Nn) {
            float4 v;
            v.x = acc[a][0] + cc.x; v.y = acc[a][1] + cc.y;
            v.z = acc[a][2] + cc.z; v.w = acc[a][3] + cc.w;
            *(float4*)&out[(size_t)r * Dd + ty * 4] = v;
        }
    }
}

// ---------------- launch ----------------
extern "C" void kernel_launch(void* const* d_in, const int* in_sizes, int n_in,
                              void* d_out, int out_size) {
    const float* feats = (const float*)d_in[0];
    const int*   src   = (const int*)d_in[1];
    const int*   dst   = (const int*)d_in[2];
    const float* W0    = (const float*)d_in[3];
    const float* b0    = (const float*)d_in[4];
    const float* W1    = (const float*)d_in[5];
    const float* b1    = (const float*)d_in[6];
    const float* W2w   = (const float*)d_in[7];
    const float* b2    = (const float*)d_in[8];
    const float* fcW   = (const float*)d_in[9];
    const float* fcb   = (const float*)d_in[10];
    const float* gamma = (const float*)d_in[11];
    const float* beta  = (const float*)d_in[12];
    const float* q     = (const float*)d_in[13];
    float* out = (float*)d_out;

    zero_deg<<<(Nn + 1023) / 1024, 1024>>>();
    count_deg<<<(Ee + 255) / 256, 256>>>(dst);
    scan1<<<NBLK1, 256>>>();
    scan2<<<1, 512>>>();
    scan3<<<NBLK1, 256>>>();
    csr_fill<<<(Ee + 255) / 256, 256>>>(src, dst);
    scale_feats<<<(Nn * 16 + 255) / 256, 256>>>(feats);

    // 3 propagations with ping-pong u buffers; h_j written into H columns
    spmm<<<(Nn + 7) / 8, 256>>>(0, 0, 1);   // reads ua, writes ub + H[:,0:64]
    spmm<<<(Nn + 7) / 8, 256>>>(1, 1, 1);   // reads ub, writes ua + H[:,64:128]
    spmm<<<(Nn + 7) / 8, 256>>>(0, 2, 0);   // reads ua, writes H[:,128:192]

    gmat<<<HIDv, 192>>>(fcW, W0, W1, W2w);
    bterm_kernel<<<2, 256>>>(fcW, fcb, b0, b1, b2);
    stats_kernel<<<STATS_BLOCKS, 256>>>();
    reduce_stats<<<(C3 * C3 + 255) / 256, 256>>>();
    bnprep<<<HIDv, 192>>>(gamma, beta);
    w2c0<<<(C3 * Dd + 255) / 256, 256>>>(q);
    out_kernel<<<(Nn + 63) / 64, 256>>>(out);
}

// round 3
// speedup vs baseline: 1.3681x; 1.3681x over previous
#include <cuda_runtime.h>
#include <cstdint>

#define Nn   100000
#define Ee   1600000
#define Dd   64
#define HIDv 512
#define C3   192
#define NBLK1 ((Nn + 255) / 256)   // 391
#define STATS_BLOCKS 148
#define KT 32                       // stats k-tile (nodes); 100000 = 32*3125 exactly
#define PADS 36                     // stats smem pad: (36 mod 32)=4 -> frag banks 4m+k bijective

// ---------------- device scratch ----------------
__device__ __align__(16) float g_ua[Nn * Dd];
__device__ __align__(16) float g_ub[Nn * Dd];
__device__ __align__(16) float g_H[(size_t)Nn * C3];
__device__ float g_norm[Nn];
__device__ float g_norm2[Nn];
__device__ int   g_deg[Nn];
__device__ int   g_rowptr[Nn + 1];
__device__ int   g_cursor[Nn];
__device__ int   g_csr[Ee];
__device__ int   g_bsum[512];
__device__ __align__(16) float g_G[HIDv * C3];
__device__ float g_bterm[HIDv];
__device__ __align__(16) float g_Cpart[(size_t)STATS_BLOCKS * C3 * C3];
__device__ float g_mHpart[STATS_BLOCKS * C3];
__device__ __align__(16) float g_Cmat[C3 * C3];
__device__ float g_mH[C3];
__device__ float g_scale[HIDv];
__device__ float g_shift[HIDv];
__device__ __align__(16) float g_W2[C3 * Dd];   // [c][o]
__device__ __align__(16) float g_c0[Dd];

__device__ __forceinline__ float tf32r(float x) {
    uint32_t u;
    asm("cvt.rna.tf32.f32 %0, %1;" : "=r"(u) : "f"(x));
    return __uint_as_float(u);
}
__device__ __forceinline__ uint32_t f2u(float x) { return __float_as_uint(x); }

__device__ __forceinline__ void mma_tf32(float4& d, uint32_t a0, uint32_t a1, uint32_t a2, uint32_t a3,
                                         uint32_t b0, uint32_t b1) {
    asm volatile(
        "mma.sync.aligned.m16n8k8.row.col.f32.tf32.tf32.f32 "
        "{%0,%1,%2,%3}, {%4,%5,%6,%7}, {%8,%9}, {%0,%1,%2,%3};"
        : "+f"(d.x), "+f"(d.y), "+f"(d.z), "+f"(d.w)
        : "r"(a0), "r"(a1), "r"(a2), "r"(a3), "r"(b0), "r"(b1));
}

// ---------------- graph preprocessing ----------------
__global__ void zero_deg() {
    int i = blockIdx.x * blockDim.x + threadIdx.x;
    if (i < Nn) g_deg[i] = 0;
}

__global__ void count_deg(const int* __restrict__ dst) {
    int e = blockIdx.x * blockDim.x + threadIdx.x;
    if (e < Ee) atomicAdd(&g_deg[dst[e]], 1);
}

__global__ void scan1() {
    __shared__ int sh[256];
    int b = blockIdx.x, t = threadIdx.x;
    int i = b * 256 + t;
    int v = (i < Nn) ? g_deg[i] : 0;
    sh[t] = v;
    __syncthreads();
    for (int off = 1; off < 256; off <<= 1) {
        int x = (t >= off) ? sh[t - off] : 0;
        __syncthreads();
        sh[t] += x;
        __syncthreads();
    }
    if (i < Nn) g_rowptr[i] = sh[t] - v;
    if (t == 255) g_bsum[b] = sh[255];
}

__global__ void scan2() {
    __shared__ int sh[512];
    int t = threadIdx.x;
    int v = (t < NBLK1) ? g_bsum[t] : 0;
    sh[t] = v;
    __syncthreads();
    for (int off = 1; off < 512; off <<= 1) {
        int x = (t >= off) ? sh[t - off] : 0;
        __syncthreads();
        sh[t] += x;
        __syncthreads();
    }
    if (t < NBLK1) g_bsum[t] = sh[t] - v;
}

__global__ void scan3() {
    int i = blockIdx.x * 256 + threadIdx.x;
    if (i < Nn) {
        int r = g_rowptr[i] + g_bsum[blockIdx.x];
        g_rowptr[i] = r;
        g_cursor[i] = r;
        int d = g_deg[i];
        float f = (d < 1) ? 1.0f : (float)d;
        float nm = rsqrtf(f);
        g_norm[i] = nm;
        g_norm2[i] = nm * nm;
        if (i == Nn - 1) g_rowptr[Nn] = Ee;
    }
}

__global__ void csr_fill(const int* __restrict__ src, const int* __restrict__ dst) {
    int e = blockIdx.x * blockDim.x + threadIdx.x;
    if (e < Ee) {
        int d = dst[e];
        int p = atomicAdd(&g_cursor[d], 1);
        g_csr[p] = src[e];
    }
}

__global__ void scale_feats(const float* __restrict__ feats) {
    int idx = blockIdx.x * blockDim.x + threadIdx.x;
    if (idx < Nn * 16) {
        int node = idx >> 4;
        float4 v = ((const float4*)feats)[idx];
        float nm = g_norm[node];
        v.x *= nm; v.y *= nm; v.z *= nm; v.w *= nm;
        ((float4*)g_ua)[idx] = v;
    }
}

// ---------------- SpMM: pull aggregation, warp per dst node ----------------
__global__ __launch_bounds__(256) void spmm(int srcbuf, int jcol, int writeU) {
    int node = blockIdx.x * 8 + (threadIdx.x >> 5);
    if (node >= Nn) return;
    int lane = threadIdx.x & 31;
    const float2* uin = (const float2*)(srcbuf ? g_ub : g_ua);
    float2* uout = (float2*)(srcbuf ? g_ua : g_ub);
    int beg = g_rowptr[node];
    int end = g_rowptr[node + 1];
    float ax = 0.f, ay = 0.f;
    int i = beg;
    for (; i + 4 <= end; i += 4) {
        int s0 = g_csr[i], s1 = g_csr[i + 1], s2 = g_csr[i + 2], s3 = g_csr[i + 3];
        float2 v0 = uin[s0 * 32 + lane];
        float2 v1 = uin[s1 * 32 + lane];
        float2 v2 = uin[s2 * 32 + lane];
        float2 v3 = uin[s3 * 32 + lane];
        ax += (v0.x + v1.x) + (v2.x + v3.x);
        ay += (v0.y + v1.y) + (v2.y + v3.y);
    }
    for (; i < end; i++) {
        float2 v = uin[g_csr[i] * 32 + lane];
        ax += v.x; ay += v.y;
    }
    float nm = g_norm[node];
    // store H pre-rounded to tf32: downstream mma consumers need no cvt
    float2 h; h.x = tf32r(ax * nm); h.y = tf32r(ay * nm);
    ((float2*)g_H)[(size_t)node * 96 + jcol * 32 + lane] = h;
    if (writeU) {
        float n2 = g_norm2[node];
        float2 u; u.x = ax * n2; u.y = ay * n2;
        uout[node * 32 + lane] = u;
    }
}

// ---------------- G = blockwise fc_W @ W_j : 4 h-rows per block ----------------
__global__ __launch_bounds__(256) void gmat(const float* __restrict__ fcW,
                                            const float* __restrict__ w0,
                                            const float* __restrict__ w1,
                                            const float* __restrict__ w2) {
    __shared__ float fw[4 * 1536];   // 24 KB
    int hb = blockIdx.x * 4;
    int tid = threadIdx.x;
    for (int i = tid; i < 4 * 1536; i += 256)
        fw[i] = fcW[(size_t)hb * 1536 + i];
    __syncthreads();
    for (int i = tid; i < 4 * 192; i += 256) {
        int hl = i / 192, c = i % 192, j = c >> 6, d = c & 63;
        const float* W = (j == 0) ? w0 : (j == 1) ? w1 : w2;
        const float* f = fw + hl * 1536 + j * 512;
        float acc = 0.f;
#pragma unroll 8
        for (int m = 0; m < 512; m++) acc = fmaf(f[m], W[m * 64 + d], acc);
        g_G[(hb + hl) * C3 + c] = acc;
    }
}

__global__ void bterm_kernel(const float* __restrict__ fcW, const float* __restrict__ fcb,
                             const float* __restrict__ b0, const float* __restrict__ b1,
                             const float* __restrict__ b2) {
    int h = blockIdx.x * blockDim.x + threadIdx.x;
    if (h >= HIDv) return;
    float acc = fcb[h];
    const float* row = fcW + (size_t)h * 1536;
    for (int m = 0; m < 512; m++)
        acc += row[m] * b0[m] + row[512 + m] * b1[m] + row[1024 + m] * b2[m];
    g_bterm[h] = acc;
}

// ---------------- stats via tf32 mma: Cpart = Hk^T Hk, mHpart = colsum ----------------
// 384 threads = 12 warps; warp w: mg=w/2 covers rows [32mg,32mg+32), ng=w%2 covers cols [96ng,96ng+96)
__global__ __launch_bounds__(384, 1) void stats_mma() {
    __shared__ float Hs[C3 * PADS];     // [c][k], 27 KB
    __shared__ float mred[384];
    int tid = threadIdx.x;
    int warp = tid >> 5, lane = tid & 31;
    int mg = warp >> 1, ng = warp & 1;
    int lr = lane >> 2, lc = lane & 3;

    float4 acc[2][12];
#pragma unroll
    for (int a = 0; a < 2; a++)
#pragma unroll
        for (int b = 0; b < 12; b++) acc[a][b] = make_float4(0.f, 0.f, 0.f, 0.f);
    float msum = 0.f;

    int cfix = tid % C3;        // 384 = 2*192: each thread loads one fixed column
    int rbase = tid / C3;       // 0 or 1

    const int ntiles = Nn / KT; // 3125 exact
    for (int tile = blockIdx.x; tile < ntiles; tile += gridDim.x) {
        int r0 = tile * KT;
        __syncthreads();
#pragma unroll
        for (int i = 0; i < KT / 2; i++) {
            int r = rbase + 2 * i;
            float v = g_H[(size_t)(r0 + r) * C3 + cfix];
            Hs[cfix * PADS + r] = v;
            msum += v;
        }
        __syncthreads();
#pragma unroll
        for (int ks = 0; ks < KT / 8; ks++) {
            int k0 = ks * 8;
            uint32_t a[2][4];
#pragma unroll
            for (int mt = 0; mt < 2; mt++) {
                int m = mg * 32 + mt * 16;
                a[mt][0] = f2u(Hs[(m + lr) * PADS + k0 + lc]);
                a[mt][1] = f2u(Hs[(m + 8 + lr) * PADS + k0 + lc]);
                a[mt][2] = f2u(Hs[(m + lr) * PADS + k0 + lc + 4]);
                a[mt][3] = f2u(Hs[(m + 8 + lr) * PADS + k0 + lc + 4]);
            }
#pragma unroll
            for (int nt = 0; nt < 12; nt++) {
                int n = ng * 96 + nt * 8;
                uint32_t b0 = f2u(Hs[(n + lr) * PADS + k0 + lc]);
                uint32_t b1 = f2u(Hs[(n + lr) * PADS + k0 + lc + 4]);
                mma_tf32(acc[0][nt], a[0][0], a[0][1], a[0][2], a[0][3], b0, b1);
                mma_tf32(acc[1][nt], a[1][0], a[1][1], a[1][2], a[1][3], b0, b1);
            }
        }
    }

    float* cp = g_Cpart + (size_t)blockIdx.x * (C3 * C3);
#pragma unroll
    for (int mt = 0; mt < 2; mt++)
#pragma unroll
        for (int nt = 0; nt < 12; nt++) {
            int row = mg * 32 + mt * 16 + lr;
            int col = ng * 96 + nt * 8 + 2 * lc;
            float4 v = acc[mt][nt];
            *(float2*)&cp[(size_t)row * C3 + col] = make_float2(v.x, v.y);
            *(float2*)&cp[(size_t)(row + 8) * C3 + col] = make_float2(v.z, v.w);
        }
    mred[tid] = msum;
    __syncthreads();
    if (tid < C3) g_mHpart[blockIdx.x * C3 + tid] = mred[tid] + mred[tid + C3];
}

__global__ void reduce_stats() {
    int i = blockIdx.x * 256 + threadIdx.x;
    const float invN = 1.0f / (float)Nn;
    if (i < C3 * C3) {
        float s = 0.f;
        for (int p = 0; p < STATS_BLOCKS; p++) s += g_Cpart[(size_t)p * (C3 * C3) + i];
        g_Cmat[i] = s * invN;
    }
    if (i < C3) {
        float s = 0.f;
        for (int p = 0; p < STATS_BLOCKS; p++) s += g_mHpart[p * C3 + i];
        g_mH[i] = s * invN;
    }
}

__global__ __launch_bounds__(192) void bnprep(const float* __restrict__ gamma,
                                              const float* __restrict__ beta) {
    int h = blockIdx.x, c = threadIdx.x;
    __shared__ float gsh[C3];
    __shared__ float red[C3], red2[C3];
    gsh[c] = g_G[h * C3 + c];
    __syncthreads();
    float t = 0.f;
    for (int cc = 0; cc < C3; cc++)
        t = fmaf(g_Cmat[cc * C3 + c], gsh[cc], t);
    red[c]  = gsh[c] * t;
    red2[c] = gsh[c] * g_mH[c];
    __syncthreads();
    if (c < 64) {
        red[c]  += red[c + 64]  + red[c + 128];
        red2[c] += red2[c + 64] + red2[c + 128];
    }
    __syncthreads();
    for (int s = 32; s > 0; s >>= 1) {
        if (c < s) { red[c] += red[c + s]; red2[c] += red2[c + s]; }
        __syncthreads();
    }
    if (c == 0) {
        float quad = red[0], dot1 = red2[0], b = g_bterm[h];
        float mu  = dot1 + b;
        float ef2 = quad + 2.f * b * dot1 + b * b;
        float var = ef2 - mu * mu;
        float sc  = rsqrtf(var + 1e-5f) * gamma[h];
        g_scale[h] = sc;
        g_shift[h] = beta[h] - mu * sc;
    }
}

__global__ void w2c0(const float* __restrict__ q) {
    int idx = blockIdx.x * blockDim.x + threadIdx.x;
    if (idx < C3 * Dd) {
        int o = idx & 63, c = idx >> 6;
        float s = 0.f;
#pragma unroll
        for (int k = 0; k < 8; k++) {
            int h = k * 64 + o;
            s += q[k] * g_scale[h] * g_G[h * C3 + c];
        }
        g_W2[c * Dd + o] = tf32r(s);   // rounded once; out kernel stages raw
    }
    if (idx < Dd) {
        float s = 0.f;
#pragma unroll
        for (int k = 0; k < 8; k++) {
            int h = k * 64 + idx;
            s += q[k] * (g_scale[h] * g_bterm[h] + g_shift[h]);
        }
        g_c0[idx] = s;
    }
}

// ---------------- out = H (Nx192) @ W2^T via tf32 mma ----------------
// block: 64 nodes, 256 threads (8 warps). warp w: m-tile mg=w/2, n-cols [32*(w&1), +32)
#define PH 68   // Hs pad: 4m+k bijective
#define PW 72   // W2s pad: 8k+n bijective
__global__ __launch_bounds__(256) void out_mma(float* __restrict__ out) {
    __shared__ float Hs[64 * PH];       // 17.4 KB
    __shared__ float W2s[64 * PW];      // 18.4 KB
    int tid = threadIdx.x;
    int warp = tid >> 5, lane = tid & 31;
    int mg = warp >> 1, ng = warp & 1;
    int lr = lane >> 2, lc = lane & 3;
    int r0 = blockIdx.x * 64;
    int nr = min(64, Nn - r0);

    float4 acc[4];
#pragma unroll
    for (int a = 0; a < 4; a++) acc[a] = make_float4(0.f, 0.f, 0.f, 0.f);

#pragma unroll
    for (int kc = 0; kc < 3; kc++) {
        __syncthreads();
        // stage H chunk [64 nodes][64 k]
#pragma unroll
        for (int i = 0; i < 16; i++) {
            int idx = tid + i * 256;
            int m = idx >> 6, kk = idx & 63;
            float v = (m < nr) ? g_H[(size_t)(r0 + m) * C3 + kc * 64 + kk] : 0.f;
            Hs[m * PH + kk] = v;
        }
        // stage W2 chunk [64 k][64 o]
#pragma unroll
        for (int i = 0; i < 16; i++) {
            int idx = tid + i * 256;
            int kk = idx >> 6, n = idx & 63;
            W2s[kk * PW + n] = g_W2[(kc * 64 + kk) * Dd + n];
        }
        __syncthreads();
#pragma unroll
        for (int ks = 0; ks < 8; ks++) {
            int k0 = ks * 8;
            int m0 = mg * 16;
            uint32_t a0 = f2u(Hs[(m0 + lr) * PH + k0 + lc]);
            uint32_t a1 = f2u(Hs[(m0 + 8 + lr) * PH + k0 + lc]);
            uint32_t a2 = f2u(Hs[(m0 + lr) * PH + k0 + lc + 4]);
            uint32_t a3 = f2u(Hs[(m0 + 8 + lr) * PH + k0 + lc + 4]);
#pragma unroll
            for (int nt = 0; nt < 4; nt++) {
                int n0 = ng * 32 + nt * 8;
                uint32_t b0 = f2u(W2s[(k0 + lc) * PW + n0 + lr]);
                uint32_t b1 = f2u(W2s[(k0 + lc + 4) * PW + n0 + lr]);
                mma_tf32(acc[nt], a0, a1, a2, a3, b0, b1);
            }
        }
    }

#pragma unroll
    for (int nt = 0; nt < 4; nt++) {
        int row = mg * 16 + lr;
        int col = ng * 32 + nt * 8 + 2 * lc;
        float2 cc = *(const float2*)&g_c0[col];
        float4 v = acc[nt];
        if (row < nr)
            *(float2*)&out[(size_t)(r0 + row) * Dd + col] = make_float2(v.x + cc.x, v.y + cc.y);
        if (row + 8 < nr)
            *(float2*)&out[(size_t)(r0 + row + 8) * Dd + col] = make_float2(v.z + cc.x, v.w + cc.y);
    }
}

// ---------------- launch ----------------
extern "C" void kernel_launch(void* const* d_in, const int* in_sizes, int n_in,
                              void* d_out, int out_size) {
    const float* feats = (const float*)d_in[0];
    const int*   src   = (const int*)d_in[1];
    const int*   dst   = (const int*)d_in[2];
    const float* W0    = (const float*)d_in[3];
    const float* b0    = (const float*)d_in[4];
    const float* W1    = (const float*)d_in[5];
    const float* b1    = (const float*)d_in[6];
    const float* W2w   = (const float*)d_in[7];
    const float* b2    = (const float*)d_in[8];
    const float* fcW   = (const float*)d_in[9];
    const float* fcb   = (const float*)d_in[10];
    const float* gamma = (const float*)d_in[11];
    const float* beta  = (const float*)d_in[12];
    const float* q     = (const float*)d_in[13];
    float* out = (float*)d_out;

    zero_deg<<<(Nn + 1023) / 1024, 1024>>>();
    count_deg<<<(Ee + 255) / 256, 256>>>(dst);
    scan1<<<NBLK1, 256>>>();
    scan2<<<1, 512>>>();
    scan3<<<NBLK1, 256>>>();
    csr_fill<<<(Ee + 255) / 256, 256>>>(src, dst);
    scale_feats<<<(Nn * 16 + 255) / 256, 256>>>(feats);

    spmm<<<(Nn + 7) / 8, 256>>>(0, 0, 1);
    spmm<<<(Nn + 7) / 8, 256>>>(1, 1, 1);
    spmm<<<(Nn + 7) / 8, 256>>>(0, 2, 0);

    gmat<<<128, 256>>>(fcW, W0, W1, W2w);
    bterm_kernel<<<2, 256>>>(fcW, fcb, b0, b1, b2);
    stats_mma<<<STATS_BLOCKS, 384>>>();
    reduce_stats<<<(C3 * C3 + 255) / 256, 256>>>();
    bnprep<<<HIDv, 192>>>(gamma, beta);
    w2c0<<<(C3 * Dd + 255) / 256, 256>>>(q);
    out_mma<<<(Nn + 63) / 64, 256>>>(out);
}

// round 5
// speedup vs baseline: 1.7117x; 1.2512x over previous
#include <cuda_runtime.h>
#include <cstdint>

#define Nn   100000
#define Ee   1600000
#define Dd   64
#define HIDv 512
#define C3   192
#define NBLK1 ((Nn + 255) / 256)   // 391
#define STATS_BLOCKS 148
#define KT 32
#define PADS 36

// ---------------- device scratch ----------------
__device__ __align__(16) float g_ua[Nn * Dd];
__device__ __align__(16) float g_ub[Nn * Dd];
__device__ __align__(16) float g_H[(size_t)Nn * C3];
__device__ float g_norm[Nn];
__device__ float g_norm2[Nn];
__device__ int   g_deg[Nn];
__device__ int   g_rowptr[Nn + 1];
__device__ int   g_cursor[Nn];
__device__ int   g_csr[Ee];
__device__ int   g_bsum[512];
__device__ int   g_barcnt[8];
__device__ __align__(16) float g_G[HIDv * C3];
__device__ float g_bterm[HIDv];
__device__ __align__(16) float g_Cpart[(size_t)STATS_BLOCKS * C3 * C3];
__device__ float g_mHpart[STATS_BLOCKS * C3];
__device__ __align__(16) float g_Cmat[C3 * C3];
__device__ float g_mH[C3];
__device__ float g_scale[HIDv];
__device__ float g_shift[HIDv];
__device__ __align__(16) float g_W2[C3 * Dd];
__device__ __align__(16) float g_c0[Dd];

__device__ __forceinline__ float tf32r(float x) {
    uint32_t u;
    asm("cvt.rna.tf32.f32 %0, %1;" : "=r"(u) : "f"(x));
    return __uint_as_float(u);
}
__device__ __forceinline__ uint32_t f2u(float x) { return __float_as_uint(x); }

__device__ __forceinline__ void mma_tf32(float4& d, uint32_t a0, uint32_t a1, uint32_t a2, uint32_t a3,
                                         uint32_t b0, uint32_t b1) {
    asm volatile(
        "mma.sync.aligned.m16n8k8.row.col.f32.tf32.tf32.f32 "
        "{%0,%1,%2,%3}, {%4,%5,%6,%7}, {%8,%9}, {%0,%1,%2,%3};"
        : "+f"(d.x), "+f"(d.y), "+f"(d.z), "+f"(d.w)
        : "r"(a0), "r"(a1), "r"(a2), "r"(a3), "r"(b0), "r"(b1));
}

// software global barrier (all NBLK1 blocks are co-resident)
__device__ __forceinline__ void gbar(int k) {
    __syncthreads();
    if (threadIdx.x == 0) {
        __threadfence();
        atomicAdd(&g_barcnt[k], 1);
        while (*(volatile int*)&g_barcnt[k] < NBLK1) { }
    }
    __syncthreads();
}

__device__ __forceinline__ void hillis256(int* sh, int t) {
#pragma unroll
    for (int off = 1; off < 256; off <<= 1) {
        int x = (t >= off) ? sh[t - off] : 0;
        __syncthreads();
        sh[t] += x;
        __syncthreads();
    }
}

// ---------------- kernel 1: zero ----------------
__global__ void zero_kernel() {
    int i = blockIdx.x * blockDim.x + threadIdx.x;
    if (i < Nn) g_deg[i] = 0;
    if (i < 8) g_barcnt[i] = 0;
}

// ---------------- kernel 2: degree count ----------------
__global__ void count_deg(const int* __restrict__ dst) {
    int e = blockIdx.x * blockDim.x + threadIdx.x;
    if (e < Ee) atomicAdd(&g_deg[dst[e]], 1);
}

// ---------------- kernel 3: fused scan + norm + scale + csr_fill ----------------
__global__ __launch_bounds__(256) void prep(const int* __restrict__ src,
                                            const int* __restrict__ dst,
                                            const float* __restrict__ feats) {
    __shared__ int sh[256];
    __shared__ float snorm[256];
    int b = blockIdx.x, t = threadIdx.x;
    int i = b * 256 + t;

    // phase A: block-local exclusive scan of degrees
    int v = (i < Nn) ? g_deg[i] : 0;
    sh[t] = v;
    __syncthreads();
    hillis256(sh, t);
    int excl = sh[t] - v;
    if (t == 255) g_bsum[b] = sh[255];
    gbar(0);

    // phase B: block 0 exclusive-scans the 391 block sums (two 256-chunks)
    if (b == 0) {
        int v1 = *(volatile int*)&g_bsum[t];
        sh[t] = v1;
        __syncthreads();
        hillis256(sh, t);
        int s1 = sh[t];
        int tot1 = sh[255];
        __syncthreads();
        int v2 = (t + 256 < NBLK1) ? *(volatile int*)&g_bsum[t + 256] : 0;
        sh[t] = v2;
        __syncthreads();
        hillis256(sh, t);
        int s2 = sh[t] + tot1;
        __syncthreads();
        g_bsum[t] = s1 - v1;
        if (t + 256 < NBLK1) g_bsum[t + 256] = s2 - v2;
    }
    gbar(1);

    // phase C: finalize rowptr/cursor/norm, scale features
    int boff = *(volatile int*)&g_bsum[b];
    float nm = 0.f;
    if (i < Nn) {
        int r = excl + boff;
        g_rowptr[i] = r;
        g_cursor[i] = r;
        int d = g_deg[i];
        float f = (d < 1) ? 1.0f : (float)d;
        nm = rsqrtf(f);
        g_norm[i] = nm;
        g_norm2[i] = nm * nm;
        if (i == Nn - 1) g_rowptr[Nn] = Ee;
    }
    snorm[t] = nm;
    __syncthreads();
    int base = b * 256;
    int nnode = min(256, Nn - base);
    if (nnode > 0) {
        const float4* f4 = (const float4*)feats;
        float4* u4 = (float4*)g_ua;
        for (int idx = t; idx < nnode * 16; idx += 256) {
            float4 vv = f4[(size_t)base * 16 + idx];
            float s = snorm[idx >> 4];
            vv.x *= s; vv.y *= s; vv.z *= s; vv.w *= s;
            u4[(size_t)base * 16 + idx] = vv;
        }
    }
    gbar(2);

    // phase D: CSR fill (grid-stride over edges)
    for (int e = b * 256 + t; e < Ee; e += NBLK1 * 256) {
        int d = dst[e];
        int p = atomicAdd(&g_cursor[d], 1);
        g_csr[p] = src[e];
    }
}

// ---------------- SpMM: pull aggregation, warp per dst node, unroll 8 ----------------
__global__ __launch_bounds__(256) void spmm(int srcbuf, int jcol, int writeU) {
    int node = blockIdx.x * 8 + (threadIdx.x >> 5);
    if (node >= Nn) return;
    int lane = threadIdx.x & 31;
    const float2* __restrict__ uin = (const float2*)(srcbuf ? g_ub : g_ua);
    float2* __restrict__ uout = (float2*)(srcbuf ? g_ua : g_ub);
    int beg = g_rowptr[node];
    int end = g_rowptr[node + 1];
    float ax0 = 0.f, ay0 = 0.f, ax1 = 0.f, ay1 = 0.f;
    int i = beg;
    for (; i + 8 <= end; i += 8) {
        int s0 = g_csr[i], s1 = g_csr[i + 1], s2 = g_csr[i + 2], s3 = g_csr[i + 3];
        int s4 = g_csr[i + 4], s5 = g_csr[i + 5], s6 = g_csr[i + 6], s7 = g_csr[i + 7];
        float2 v0 = uin[s0 * 32 + lane];
        float2 v1 = uin[s1 * 32 + lane];
        float2 v2 = uin[s2 * 32 + lane];
        float2 v3 = uin[s3 * 32 + lane];
        float2 v4 = uin[s4 * 32 + lane];
        float2 v5 = uin[s5 * 32 + lane];
        float2 v6 = uin[s6 * 32 + lane];
        float2 v7 = uin[s7 * 32 + lane];
        ax0 += (v0.x + v1.x) + (v2.x + v3.x);
        ay0 += (v0.y + v1.y) + (v2.y + v3.y);
        ax1 += (v4.x + v5.x) + (v6.x + v7.x);
        ay1 += (v4.y + v5.y) + (v6.y + v7.y);
    }
    for (; i + 2 <= end; i += 2) {
        int s0 = g_csr[i], s1 = g_csr[i + 1];
        float2 v0 = uin[s0 * 32 + lane];
        float2 v1 = uin[s1 * 32 + lane];
        ax0 += v0.x + v1.x;
        ay0 += v0.y + v1.y;
    }
    if (i < end) {
        float2 v = uin[g_csr[i] * 32 + lane];
        ax1 += v.x; ay1 += v.y;
    }
    float ax = ax0 + ax1, ay = ay0 + ay1;
    float nm = g_norm[node];
    float2 h; h.x = tf32r(ax * nm); h.y = tf32r(ay * nm);
    ((float2*)g_H)[(size_t)node * 96 + jcol * 32 + lane] = h;
    if (writeU) {
        float n2 = g_norm2[node];
        float2 u; u.x = ax * n2; u.y = ay * n2;
        uout[node * 32 + lane] = u;
    }
}

// ---------------- G = blockwise fc_W @ W_j + bterm, 4 h-rows/block ----------------
__global__ __launch_bounds__(256) void gmatb(const float* __restrict__ fcW,
                                             const float* __restrict__ w0,
                                             const float* __restrict__ w1,
                                             const float* __restrict__ w2,
                                             const float* __restrict__ fcb,
                                             const float* __restrict__ b0,
                                             const float* __restrict__ b1,
                                             const float* __restrict__ b2) {
    __shared__ float fw[4 * 1536];
    __shared__ float red[256];
    int hb = blockIdx.x * 4;
    int tid = threadIdx.x;
    for (int i = tid; i < 4 * 1536; i += 256)
        fw[i] = fcW[(size_t)hb * 1536 + i];
    __syncthreads();
    for (int i = tid; i < 4 * 192; i += 256) {
        int hl = i / 192, c = i % 192, j = c >> 6, d = c & 63;
        const float* W = (j == 0) ? w0 : (j == 1) ? w1 : w2;
        const float* f = fw + hl * 1536 + j * 512;
        float acc = 0.f;
#pragma unroll 8
        for (int m = 0; m < 512; m++) acc = fmaf(f[m], W[m * 64 + d], acc);
        g_G[(hb + hl) * C3 + c] = acc;
    }
    // bterm for the 4 rows
    for (int r = 0; r < 4; r++) {
        float p = 0.f;
        for (int m = tid; m < 1536; m += 256) {
            float bv = (m < 512) ? b0[m] : (m < 1024) ? b1[m - 512] : b2[m - 1024];
            p = fmaf(fw[r * 1536 + m], bv, p);
        }
        red[tid] = p;
        __syncthreads();
        for (int s = 128; s > 0; s >>= 1) {
            if (tid < s) red[tid] += red[tid + s];
            __syncthreads();
        }
        if (tid == 0) g_bterm[hb + r] = red[0] + fcb[hb + r];
        __syncthreads();
    }
}

// ---------------- stats via tf32 mma ----------------
__global__ __launch_bounds__(384, 1) void stats_mma() {
    __shared__ float Hs[C3 * PADS];
    __shared__ float mred[384];
    int tid = threadIdx.x;
    int warp = tid >> 5, lane = tid & 31;
    int mg = warp >> 1, ng = warp & 1;
    int lr = lane >> 2, lc = lane & 3;

    float4 acc[2][12];
#pragma unroll
    for (int a = 0; a < 2; a++)
#pragma unroll
        for (int b = 0; b < 12; b++) acc[a][b] = make_float4(0.f, 0.f, 0.f, 0.f);
    float msum = 0.f;

    int cfix = tid % C3;
    int rbase = tid / C3;

    const int ntiles = Nn / KT;
    for (int tile = blockIdx.x; tile < ntiles; tile += gridDim.x) {
        int r0 = tile * KT;
        __syncthreads();
#pragma unroll
        for (int i = 0; i < KT / 2; i++) {
            int r = rbase + 2 * i;
            float v = g_H[(size_t)(r0 + r) * C3 + cfix];
            Hs[cfix * PADS + r] = v;
            msum += v;
        }
        __syncthreads();
#pragma unroll
        for (int ks = 0; ks < KT / 8; ks++) {
            int k0 = ks * 8;
            uint32_t a[2][4];
#pragma unroll
            for (int mt = 0; mt < 2; mt++) {
                int m = mg * 32 + mt * 16;
                a[mt][0] = f2u(Hs[(m + lr) * PADS + k0 + lc]);
                a[mt][1] = f2u(Hs[(m + 8 + lr) * PADS + k0 + lc]);
                a[mt][2] = f2u(Hs[(m + lr) * PADS + k0 + lc + 4]);
                a[mt][3] = f2u(Hs[(m + 8 + lr) * PADS + k0 + lc + 4]);
            }
#pragma unroll
            for (int nt = 0; nt < 12; nt++) {
                int n = ng * 96 + nt * 8;
                uint32_t b0 = f2u(Hs[(n + lr) * PADS + k0 + lc]);
                uint32_t b1 = f2u(Hs[(n + lr) * PADS + k0 + lc + 4]);
                mma_tf32(acc[0][nt], a[0][0], a[0][1], a[0][2], a[0][3], b0, b1);
                mma_tf32(acc[1][nt], a[1][0], a[1][1], a[1][2], a[1][3], b0, b1);
            }
        }
    }

    float* cp = g_Cpart + (size_t)blockIdx.x * (C3 * C3);
#pragma unroll
    for (int mt = 0; mt < 2; mt++)
#pragma unroll
        for (int nt = 0; nt < 12; nt++) {
            int row = mg * 32 + mt * 16 + lr;
            int col = ng * 96 + nt * 8 + 2 * lc;
            float4 v = acc[mt][nt];
            *(float2*)&cp[(size_t)row * C3 + col] = make_float2(v.x, v.y);
            *(float2*)&cp[(size_t)(row + 8) * C3 + col] = make_float2(v.z, v.w);
        }
    mred[tid] = msum;
    __syncthreads();
    if (tid < C3) g_mHpart[blockIdx.x * C3 + tid] = mred[tid] + mred[tid + C3];
}

__global__ void reduce_stats() {
    int i = blockIdx.x * 256 + threadIdx.x;
    const float invN = 1.0f / (float)Nn;
    if (i < C3 * C3) {
        float s = 0.f;
        for (int p = 0; p < STATS_BLOCKS; p++) s += g_Cpart[(size_t)p * (C3 * C3) + i];
        g_Cmat[i] = s * invN;
    }
    if (i < C3) {
        float s = 0.f;
        for (int p = 0; p < STATS_BLOCKS; p++) s += g_mHpart[p * C3 + i];
        g_mH[i] = s * invN;
    }
}

__global__ __launch_bounds__(192) void bnprep(const float* __restrict__ gamma,
                                              const float* __restrict__ beta) {
    int h = blockIdx.x, c = threadIdx.x;
    __shared__ float gsh[C3];
    __shared__ float red[C3], red2[C3];
    gsh[c] = g_G[h * C3 + c];
    __syncthreads();
    float t = 0.f;
    for (int cc = 0; cc < C3; cc++)
        t = fmaf(g_Cmat[cc * C3 + c], gsh[cc], t);
    red[c]  = gsh[c] * t;
    red2[c] = gsh[c] * g_mH[c];
    __syncthreads();
    if (c < 64) {
        red[c]  += red[c + 64]  + red[c + 128];
        red2[c] += red2[c + 64] + red2[c + 128];
    }
    __syncthreads();
    for (int s = 32; s > 0; s >>= 1) {
        if (c < s) { red[c] += red[c + s]; red2[c] += red2[c + s]; }
        __syncthreads();
    }
    if (c == 0) {
        float quad = red[0], dot1 = red2[0], b = g_bterm[h];
        float mu  = dot1 + b;
        float ef2 = quad + 2.f * b * dot1 + b * b;
        float var = ef2 - mu * mu;
        float sc  = rsqrtf(var + 1e-5f) * gamma[h];
        g_scale[h] = sc;
        g_shift[h] = beta[h] - mu * sc;
    }
}

__global__ void w2c0(const float* __restrict__ q) {
    int idx = blockIdx.x * blockDim.x + threadIdx.x;
    if (idx < C3 * Dd) {
        int o = idx & 63, c = idx >> 6;
        float s = 0.f;
#pragma unroll
        for (int k = 0; k < 8; k++) {
            int h = k * 64 + o;
            s += q[k] * g_scale[h] * g_G[h * C3 + c];
        }
        g_W2[c * Dd + o] = tf32r(s);
    }
    if (idx < Dd) {
        float s = 0.f;
#pragma unroll
        for (int k = 0; k < 8; k++) {
            int h = k * 64 + idx;
            s += q[k] * (g_scale[h] * g_bterm[h] + g_shift[h]);
        }
        g_c0[idx] = s;
    }
}

// ---------------- out = H (Nx192) @ W2^T via tf32 mma ----------------
#define PH 68
#define PW 72
__global__ __launch_bounds__(256) void out_mma(float* __restrict__ out) {
    __shared__ float Hs[64 * PH];
    __shared__ float W2s[64 * PW];
    int tid = threadIdx.x;
    int warp = tid >> 5, lane = tid & 31;
    int mg = warp >> 1, ng = warp & 1;
    int lr = lane >> 2, lc = lane & 3;
    int r0 = blockIdx.x * 64;
    int nr = min(64, Nn - r0);

    float4 acc[4];
#pragma unroll
    for (int a = 0; a < 4; a++) acc[a] = make_float4(0.f, 0.f, 0.f, 0.f);

#pragma unroll
    for (int kc = 0; kc < 3; kc++) {
        __syncthreads();
#pragma unroll
        for (int i = 0; i < 4; i++) {
            int idx4 = tid + i * 256;
            int m = idx4 >> 4, k4 = (idx4 & 15) << 2;
            float4 v = make_float4(0.f, 0.f, 0.f, 0.f);
            if (m < nr) v = *(const float4*)&g_H[(size_t)(r0 + m) * C3 + kc * 64 + k4];
            *(float4*)&Hs[m * PH + k4] = v;
        }
#pragma unroll
        for (int i = 0; i < 4; i++) {
            int idx4 = tid + i * 256;
            int k = idx4 >> 4, n4 = (idx4 & 15) << 2;
            *(float4*)&W2s[k * PW + n4] = *(const float4*)&g_W2[(kc * 64 + k) * Dd + n4];
        }
        __syncthreads();
#pragma unroll
        for (int ks = 0; ks < 8; ks++) {
            int k0 = ks * 8;
            int m0 = mg * 16;
            uint32_t a0 = f2u(Hs[(m0 + lr) * PH + k0 + lc]);
            uint32_t a1 = f2u(Hs[(m0 + 8 + lr) * PH + k0 + lc]);
            uint32_t a2 = f2u(Hs[(m0 + lr) * PH + k0 + lc + 4]);
            uint32_t a3 = f2u(Hs[(m0 + 8 + lr) * PH + k0 + lc + 4]);
#pragma unroll
            for (int nt = 0; nt < 4; nt++) {
                int n0 = ng * 32 + nt * 8;
                uint32_t b0 = f2u(W2s[(k0 + lc) * PW + n0 + lr]);
                uint32_t b1 = f2u(W2s[(k0 + lc + 4) * PW + n0 + lr]);
                mma_tf32(acc[nt], a0, a1, a2, a3, b0, b1);
            }
        }
    }

#pragma unroll
    for (int nt = 0; nt < 4; nt++) {
        int row = mg * 16 + lr;
        int col = ng * 32 + nt * 8 + 2 * lc;
        float2 cc = *(const float2*)&g_c0[col];
        float4 v = acc[nt];
        if (row < nr)
            *(float2*)&out[(size_t)(r0 + row) * Dd + col] = make_float2(v.x + cc.x, v.y + cc.y);
        if (row + 8 < nr)
            *(float2*)&out[(size_t)(r0 + row + 8) * Dd + col] = make_float2(v.z + cc.x, v.w + cc.y);
    }
}

// ---------------- launch ----------------
extern "C" void kernel_launch(void* const* d_in, const int* in_sizes, int n_in,
                              void* d_out, int out_size) {
    const float* feats = (const float*)d_in[0];
    const int*   src   = (const int*)d_in[1];
    const int*   dst   = (const int*)d_in[2];
    const float* W0    = (const float*)d_in[3];
    const float* b0    = (const float*)d_in[4];
    const float* W1    = (const float*)d_in[5];
    const float* b1    = (const float*)d_in[6];
    const float* W2w   = (const float*)d_in[7];
    const float* b2    = (const float*)d_in[8];
    const float* fcW   = (const float*)d_in[9];
    const float* fcb   = (const float*)d_in[10];
    const float* gamma = (const float*)d_in[11];
    const float* beta  = (const float*)d_in[12];
    const float* q     = (const float*)d_in[13];
    float* out = (float*)d_out;

    zero_kernel<<<(Nn + 1023) / 1024, 1024>>>();                 // launch 1
    count_deg<<<(Ee + 255) / 256, 256>>>(dst);                   // launch 2
    prep<<<NBLK1, 256>>>(src, dst, feats);                       // launch 3 (scan+norm+scale+csr)
    spmm<<<(Nn + 7) / 8, 256>>>(0, 0, 1);                        // launch 4 <- ncu window
    spmm<<<(Nn + 7) / 8, 256>>>(1, 1, 1);                        // launch 5
    spmm<<<(Nn + 7) / 8, 256>>>(0, 2, 0);                        // launch 6
    gmatb<<<128, 256>>>(fcW, W0, W1, W2w, fcb, b0, b1, b2);      // launch 7
    stats_mma<<<STATS_BLOCKS, 384>>>();                          // launch 8
    reduce_stats<<<(C3 * C3 + 255) / 256, 256>>>();              // launch 9
    bnprep<<<HIDv, 192>>>(gamma, beta);                          // launch 10
    w2c0<<<(C3 * Dd + 255) / 256, 256>>>(q);                     // launch 11
    out_mma<<<(Nn + 63) / 64, 256>>>(out);                       // launch 12
}

// round 6
// speedup vs baseline: 2.0938x; 1.2232x over previous
#include <cuda_runtime.h>
#include <cstdint>

#define Nn   100000
#define Ee   1600000
#define Dd   64
#define HIDv 512
#define C3   192
#define NBLK1 ((Nn + 255) / 256)   // 391
#define STATS_BLOCKS 148
#define KT 32
#define PADS 36

// ---------------- device scratch ----------------
__device__ __align__(16) float g_ua[Nn * Dd];
__device__ __align__(16) float g_ub[Nn * Dd];
__device__ __align__(16) float g_H[(size_t)Nn * C3];
__device__ float g_norm[Nn];
__device__ float g_norm2[Nn];
__device__ int   g_deg[Nn];
__device__ int   g_rowptr[Nn + 1];
__device__ int   g_cursor[Nn];
__device__ int   g_csr[Ee];
__device__ int   g_bsum[512];
__device__ int   g_barcnt[8];
__device__ __align__(16) float g_G[HIDv * C3];
__device__ float g_bterm[HIDv];
__device__ __align__(16) float g_Cpart[(size_t)STATS_BLOCKS * C3 * C3];
__device__ float g_mHpart[STATS_BLOCKS * C3];
__device__ __align__(16) float g_Cmat[C3 * C3];
__device__ float g_mH[C3];
__device__ float g_scale[HIDv];
__device__ float g_shift[HIDv];
__device__ __align__(16) float g_W2[C3 * Dd];
__device__ __align__(16) float g_c0[Dd];

__device__ __forceinline__ float tf32r(float x) {
    uint32_t u;
    asm("cvt.rna.tf32.f32 %0, %1;" : "=r"(u) : "f"(x));
    return __uint_as_float(u);
}
__device__ __forceinline__ uint32_t f2u(float x) { return __float_as_uint(x); }

__device__ __forceinline__ void mma_tf32(float4& d, uint32_t a0, uint32_t a1, uint32_t a2, uint32_t a3,
                                         uint32_t b0, uint32_t b1) {
    asm volatile(
        "mma.sync.aligned.m16n8k8.row.col.f32.tf32.tf32.f32 "
        "{%0,%1,%2,%3}, {%4,%5,%6,%7}, {%8,%9}, {%0,%1,%2,%3};"
        : "+f"(d.x), "+f"(d.y), "+f"(d.z), "+f"(d.w)
        : "r"(a0), "r"(a1), "r"(a2), "r"(a3), "r"(b0), "r"(b1));
}

// software global barrier (all NBLK1 blocks co-resident)
__device__ __forceinline__ void gbar(int k) {
    __syncthreads();
    if (threadIdx.x == 0) {
        __threadfence();
        atomicAdd(&g_barcnt[k], 1);
        while (*(volatile int*)&g_barcnt[k] < NBLK1) { }
    }
    __syncthreads();
}

__device__ __forceinline__ void hillis256(int* sh, int t) {
#pragma unroll
    for (int off = 1; off < 256; off <<= 1) {
        int x = (t >= off) ? sh[t - off] : 0;
        __syncthreads();
        sh[t] += x;
        __syncthreads();
    }
}

// ---------------- kernel 1: zero ----------------
__global__ void zero_kernel() {
    int i = blockIdx.x * blockDim.x + threadIdx.x;
    if (i < Nn) g_deg[i] = 0;
    if (i < 8) g_barcnt[i] = 0;
}

// ---------------- kernel 2: fused count + scan + norm + scale + csr_fill ----------------
__global__ __launch_bounds__(256) void prep(const int* __restrict__ src,
                                            const int* __restrict__ dst,
                                            const float* __restrict__ feats) {
    __shared__ int sh[256];
    __shared__ float snorm[256];
    int b = blockIdx.x, t = threadIdx.x;
    int i = b * 256 + t;

    // phase A0: degree histogram (grid-stride, no-return atomics -> RED)
    for (int e = b * 256 + t; e < Ee; e += NBLK1 * 256)
        atomicAdd(&g_deg[dst[e]], 1);
    gbar(0);

    // phase A: block-local exclusive scan of degrees
    int v = (i < Nn) ? g_deg[i] : 0;
    sh[t] = v;
    __syncthreads();
    hillis256(sh, t);
    int excl = sh[t] - v;
    if (t == 255) g_bsum[b] = sh[255];
    gbar(1);

    // phase B: block 0 scans the 391 block sums
    if (b == 0) {
        int v1 = *(volatile int*)&g_bsum[t];
        sh[t] = v1;
        __syncthreads();
        hillis256(sh, t);
        int s1 = sh[t];
        int tot1 = sh[255];
        __syncthreads();
        int v2 = (t + 256 < NBLK1) ? *(volatile int*)&g_bsum[t + 256] : 0;
        sh[t] = v2;
        __syncthreads();
        hillis256(sh, t);
        int s2 = sh[t] + tot1;
        __syncthreads();
        g_bsum[t] = s1 - v1;
        if (t + 256 < NBLK1) g_bsum[t + 256] = s2 - v2;
    }
    gbar(2);

    // phase C: finalize rowptr/cursor/norm, scale features
    int boff = *(volatile int*)&g_bsum[b];
    float nm = 0.f;
    if (i < Nn) {
        int r = excl + boff;
        g_rowptr[i] = r;
        g_cursor[i] = r;
        float f = (v < 1) ? 1.0f : (float)v;
        nm = rsqrtf(f);
        g_norm[i] = nm;
        g_norm2[i] = nm * nm;
        if (i == Nn - 1) g_rowptr[Nn] = Ee;
    }
    snorm[t] = nm;
    __syncthreads();
    int base = b * 256;
    int nnode = min(256, Nn - base);
    if (nnode > 0) {
        const float4* f4 = (const float4*)feats;
        float4* u4 = (float4*)g_ua;
        for (int idx = t; idx < nnode * 16; idx += 256) {
            float4 vv = f4[(size_t)base * 16 + idx];
            float s = snorm[idx >> 4];
            vv.x *= s; vv.y *= s; vv.z *= s; vv.w *= s;
            u4[(size_t)base * 16 + idx] = vv;
        }
    }
    gbar(3);

    // phase D: CSR fill (grid-stride over edges)
    for (int e = b * 256 + t; e < Ee; e += NBLK1 * 256) {
        int d = dst[e];
        int p = atomicAdd(&g_cursor[d], 1);
        g_csr[p] = src[e];
    }
}

// ---------------- SpMM: warp per dst node, 2 edges/load via half-warp float4 ----------------
__global__ __launch_bounds__(256) void spmm(int srcbuf, int jcol, int writeU) {
    int node = blockIdx.x * 8 + (threadIdx.x >> 5);
    if (node >= Nn) return;
    int lane = threadIdx.x & 31;
    int q = lane & 15, half = lane >> 4;
    const float4* __restrict__ uin = (const float4*)(srcbuf ? g_ub : g_ua);
    float4* __restrict__ uout = (float4*)(srcbuf ? g_ua : g_ub);
    int beg = g_rowptr[node];
    int end = g_rowptr[node + 1];
    float4 accA = make_float4(0.f, 0.f, 0.f, 0.f);
    float4 accB = make_float4(0.f, 0.f, 0.f, 0.f);
    int i = beg;
    for (; i + 8 <= end; i += 8) {
        // one coalesced load of 8 indices, distribute via shfl
        int cv = g_csr[i + (lane & 7)];
        int s0 = __shfl_sync(0xffffffffu, cv, half);
        int s1 = __shfl_sync(0xffffffffu, cv, 2 + half);
        int s2 = __shfl_sync(0xffffffffu, cv, 4 + half);
        int s3 = __shfl_sync(0xffffffffu, cv, 6 + half);
        float4 v0 = uin[s0 * 16 + q];
        float4 v1 = uin[s1 * 16 + q];
        float4 v2 = uin[s2 * 16 + q];
        float4 v3 = uin[s3 * 16 + q];
        accA.x += v0.x + v1.x; accA.y += v0.y + v1.y;
        accA.z += v0.z + v1.z; accA.w += v0.w + v1.w;
        accB.x += v2.x + v3.x; accB.y += v2.y + v3.y;
        accB.z += v2.z + v3.z; accB.w += v2.w + v3.w;
    }
    for (; i < end; i += 2) {
        int e = i + half;
        if (e < end) {
            int s = g_csr[e];
            float4 v = uin[s * 16 + q];
            accA.x += v.x; accA.y += v.y; accA.z += v.z; accA.w += v.w;
        }
    }
    accA.x += accB.x; accA.y += accB.y; accA.z += accB.z; accA.w += accB.w;
    accA.x += __shfl_xor_sync(0xffffffffu, accA.x, 16);
    accA.y += __shfl_xor_sync(0xffffffffu, accA.y, 16);
    accA.z += __shfl_xor_sync(0xffffffffu, accA.z, 16);
    accA.w += __shfl_xor_sync(0xffffffffu, accA.w, 16);
    if (half == 0) {
        float nm = g_norm[node];
        float4 h;
        h.x = tf32r(accA.x * nm); h.y = tf32r(accA.y * nm);
        h.z = tf32r(accA.z * nm); h.w = tf32r(accA.w * nm);
        ((float4*)g_H)[(size_t)node * 48 + jcol * 16 + q] = h;
        if (writeU) {
            float n2 = g_norm2[node];
            float4 u;
            u.x = accA.x * n2; u.y = accA.y * n2;
            u.z = accA.z * n2; u.w = accA.w * n2;
            uout[node * 16 + q] = u;
        }
    }
}

// ---------------- G = blockwise fc_W @ W_j + bterm, 4 h-rows/block ----------------
__global__ __launch_bounds__(256) void gmatb(const float* __restrict__ fcW,
                                             const float* __restrict__ w0,
                                             const float* __restrict__ w1,
                                             const float* __restrict__ w2,
                                             const float* __restrict__ fcb,
                                             const float* __restrict__ b0,
                                             const float* __restrict__ b1,
                                             const float* __restrict__ b2) {
    __shared__ float fw[4 * 1536];
    __shared__ float red[256];
    int hb = blockIdx.x * 4;
    int tid = threadIdx.x;
    for (int i = tid; i < 4 * 1536; i += 256)
        fw[i] = fcW[(size_t)hb * 1536 + i];
    __syncthreads();
    for (int i = tid; i < 4 * 192; i += 256) {
        int hl = i / 192, c = i % 192, j = c >> 6, d = c & 63;
        const float* W = (j == 0) ? w0 : (j == 1) ? w1 : w2;
        const float* f = fw + hl * 1536 + j * 512;
        float acc = 0.f;
#pragma unroll 8
        for (int m = 0; m < 512; m++) acc = fmaf(f[m], W[m * 64 + d], acc);
        g_G[(hb + hl) * C3 + c] = acc;
    }
    for (int r = 0; r < 4; r++) {
        float p = 0.f;
        for (int m = tid; m < 1536; m += 256) {
            float bv = (m < 512) ? b0[m] : (m < 1024) ? b1[m - 512] : b2[m - 1024];
            p = fmaf(fw[r * 1536 + m], bv, p);
        }
        red[tid] = p;
        __syncthreads();
        for (int s = 128; s > 0; s >>= 1) {
            if (tid < s) red[tid] += red[tid + s];
            __syncthreads();
        }
        if (tid == 0) g_bterm[hb + r] = red[0] + fcb[hb + r];
        __syncthreads();
    }
}

// ---------------- stats via tf32 mma ----------------
__global__ __launch_bounds__(384, 1) void stats_mma() {
    __shared__ float Hs[C3 * PADS];
    __shared__ float mred[384];
    int tid = threadIdx.x;
    int warp = tid >> 5, lane = tid & 31;
    int mg = warp >> 1, ng = warp & 1;
    int lr = lane >> 2, lc = lane & 3;

    float4 acc[2][12];
#pragma unroll
    for (int a = 0; a < 2; a++)
#pragma unroll
        for (int b = 0; b < 12; b++) acc[a][b] = make_float4(0.f, 0.f, 0.f, 0.f);
    float msum = 0.f;

    int cfix = tid % C3;
    int rbase = tid / C3;

    const int ntiles = Nn / KT;
    for (int tile = blockIdx.x; tile < ntiles; tile += gridDim.x) {
        int r0 = tile * KT;
        __syncthreads();
#pragma unroll
        for (int i = 0; i < KT / 2; i++) {
            int r = rbase + 2 * i;
            float v = g_H[(size_t)(r0 + r) * C3 + cfix];
            Hs[cfix * PADS + r] = v;
            msum += v;
        }
        __syncthreads();
#pragma unroll
        for (int ks = 0; ks < KT / 8; ks++) {
            int k0 = ks * 8;
            uint32_t a[2][4];
#pragma unroll
            for (int mt = 0; mt < 2; mt++) {
                int m = mg * 32 + mt * 16;
                a[mt][0] = f2u(Hs[(m + lr) * PADS + k0 + lc]);
                a[mt][1] = f2u(Hs[(m + 8 + lr) * PADS + k0 + lc]);
                a[mt][2] = f2u(Hs[(m + lr) * PADS + k0 + lc + 4]);
                a[mt][3] = f2u(Hs[(m + 8 + lr) * PADS + k0 + lc + 4]);
            }
#pragma unroll
            for (int nt = 0; nt < 12; nt++) {
                int n = ng * 96 + nt * 8;
                uint32_t b0 = f2u(Hs[(n + lr) * PADS + k0 + lc]);
                uint32_t b1 = f2u(Hs[(n + lr) * PADS + k0 + lc + 4]);
                mma_tf32(acc[0][nt], a[0][0], a[0][1], a[0][2], a[0][3], b0, b1);
                mma_tf32(acc[1][nt], a[1][0], a[1][1], a[1][2], a[1][3], b0, b1);
            }
        }
    }

    float* cp = g_Cpart + (size_t)blockIdx.x * (C3 * C3);
#pragma unroll
    for (int mt = 0; mt < 2; mt++)
#pragma unroll
        for (int nt = 0; nt < 12; nt++) {
            int row = mg * 32 + mt * 16 + lr;
            int col = ng * 96 + nt * 8 + 2 * lc;
            float4 v = acc[mt][nt];
            *(float2*)&cp[(size_t)row * C3 + col] = make_float2(v.x, v.y);
            *(float2*)&cp[(size_t)(row + 8) * C3 + col] = make_float2(v.z, v.w);
        }
    mred[tid] = msum;
    __syncthreads();
    if (tid < C3) g_mHpart[blockIdx.x * C3 + tid] = mred[tid] + mred[tid + C3];
}

__global__ void reduce_stats() {
    int i = blockIdx.x * 256 + threadIdx.x;
    const float invN = 1.0f / (float)Nn;
    if (i < C3 * C3) {
        float s = 0.f;
        for (int p = 0; p < STATS_BLOCKS; p++) s += g_Cpart[(size_t)p * (C3 * C3) + i];
        g_Cmat[i] = s * invN;
    }
    if (i < C3) {
        float s = 0.f;
        for (int p = 0; p < STATS_BLOCKS; p++) s += g_mHpart[p * C3 + i];
        g_mH[i] = s * invN;
    }
}

// 4 h per block: Cmat column stream reused for 4 rows
__global__ __launch_bounds__(192) void bnprep(const float* __restrict__ gamma,
                                              const float* __restrict__ beta) {
    int hb = blockIdx.x * 4, c = threadIdx.x;
    __shared__ float gsh[4][C3];
    __shared__ float red[C3], red2[C3];
#pragma unroll
    for (int j = 0; j < 4; j++) gsh[j][c] = g_G[(hb + j) * C3 + c];
    __syncthreads();
    float t0 = 0.f, t1 = 0.f, t2 = 0.f, t3 = 0.f;
    for (int cc = 0; cc < C3; cc++) {
        float cm = g_Cmat[cc * C3 + c];
        t0 = fmaf(cm, gsh[0][cc], t0);
        t1 = fmaf(cm, gsh[1][cc], t1);
        t2 = fmaf(cm, gsh[2][cc], t2);
        t3 = fmaf(cm, gsh[3][cc], t3);
    }
    float mh = g_mH[c];
    float ts[4] = {t0, t1, t2, t3};
#pragma unroll
    for (int j = 0; j < 4; j++) {
        __syncthreads();
        red[c]  = gsh[j][c] * ts[j];
        red2[c] = gsh[j][c] * mh;
        __syncthreads();
        if (c < 64) {
            red[c]  += red[c + 64]  + red[c + 128];
            red2[c] += red2[c + 64] + red2[c + 128];
        }
        __syncthreads();
        for (int s = 32; s > 0; s >>= 1) {
            if (c < s) { red[c] += red[c + s]; red2[c] += red2[c + s]; }
            __syncthreads();
        }
        if (c == 0) {
            int h = hb + j;
            float quad = red[0], dot1 = red2[0], b = g_bterm[h];
            float mu  = dot1 + b;
            float ef2 = quad + 2.f * b * dot1 + b * b;
            float var = ef2 - mu * mu;
            float sc  = rsqrtf(var + 1e-5f) * gamma[h];
            g_scale[h] = sc;
            g_shift[h] = beta[h] - mu * sc;
        }
    }
}

__global__ void w2c0(const float* __restrict__ q) {
    int idx = blockIdx.x * blockDim.x + threadIdx.x;
    if (idx < C3 * Dd) {
        int o = idx & 63, c = idx >> 6;
        float s = 0.f;
#pragma unroll
        for (int k = 0; k < 8; k++) {
            int h = k * 64 + o;
            s += q[k] * g_scale[h] * g_G[h * C3 + c];
        }
        g_W2[c * Dd + o] = tf32r(s);
    }
    if (idx < Dd) {
        float s = 0.f;
#pragma unroll
        for (int k = 0; k < 8; k++) {
            int h = k * 64 + idx;
            s += q[k] * (g_scale[h] * g_bterm[h] + g_shift[h]);
        }
        g_c0[idx] = s;
    }
}

// ---------------- out = H (Nx192) @ W2^T via tf32 mma ----------------
#define PH 68
#define PW 72
__global__ __launch_bounds__(256) void out_mma(float* __restrict__ out) {
    __shared__ float Hs[64 * PH];
    __shared__ float W2s[64 * PW];
    int tid = threadIdx.x;
    int warp = tid >> 5, lane = tid & 31;
    int mg = warp >> 1, ng = warp & 1;
    int lr = lane >> 2, lc = lane & 3;
    int r0 = blockIdx.x * 64;
    int nr = min(64, Nn - r0);

    float4 acc[4];
#pragma unroll
    for (int a = 0; a < 4; a++) acc[a] = make_float4(0.f, 0.f, 0.f, 0.f);

#pragma unroll
    for (int kc = 0; kc < 3; kc++) {
        __syncthreads();
#pragma unroll
        for (int i = 0; i < 4; i++) {
            int idx4 = tid + i * 256;
            int m = idx4 >> 4, k4 = (idx4 & 15) << 2;
            float4 v = make_float4(0.f, 0.f, 0.f, 0.f);
            if (m < nr) v = *(const float4*)&g_H[(size_t)(r0 + m) * C3 + kc * 64 + k4];
            *(float4*)&Hs[m * PH + k4] = v;
        }
#pragma unroll
        for (int i = 0; i < 4; i++) {
            int idx4 = tid + i * 256;
            int k = idx4 >> 4, n4 = (idx4 & 15) << 2;
            *(float4*)&W2s[k * PW + n4] = *(const float4*)&g_W2[(kc * 64 + k) * Dd + n4];
        }
        __syncthreads();
#pragma unroll
        for (int ks = 0; ks < 8; ks++) {
            int k0 = ks * 8;
            int m0 = mg * 16;
            uint32_t a0 = f2u(Hs[(m0 + lr) * PH + k0 + lc]);
            uint32_t a1 = f2u(Hs[(m0 + 8 + lr) * PH + k0 + lc]);
            uint32_t a2 = f2u(Hs[(m0 + lr) * PH + k0 + lc + 4]);
            uint32_t a3 = f2u(Hs[(m0 + 8 + lr) * PH + k0 + lc + 4]);
#pragma unroll
            for (int nt = 0; nt < 4; nt++) {
                int n0 = ng * 32 + nt * 8;
                uint32_t b0 = f2u(W2s[(k0 + lc) * PW + n0 + lr]);
                uint32_t b1 = f2u(W2s[(k0 + lc + 4) * PW + n0 + lr]);
                mma_tf32(acc[nt], a0, a1, a2, a3, b0, b1);
            }
        }
    }

#pragma unroll
    for (int nt = 0; nt < 4; nt++) {
        int row = mg * 16 + lr;
        int col = ng * 32 + nt * 8 + 2 * lc;
        float2 cc = *(const float2*)&g_c0[col];
        float4 v = acc[nt];
        if (row < nr)
            *(float2*)&out[(size_t)(r0 + row) * Dd + col] = make_float2(v.x + cc.x, v.y + cc.y);
        if (row + 8 < nr)
            *(float2*)&out[(size_t)(r0 + row + 8) * Dd + col] = make_float2(v.z + cc.x, v.w + cc.y);
    }
}

// ---------------- launch ----------------
extern "C" void kernel_launch(void* const* d_in, const int* in_sizes, int n_in,
                              void* d_out, int out_size) {
    const float* feats = (const float*)d_in[0];
    const int*   src   = (const int*)d_in[1];
    const int*   dst   = (const int*)d_in[2];
    const float* W0    = (const float*)d_in[3];
    const float* b0    = (const float*)d_in[4];
    const float* W1    = (const float*)d_in[5];
    const float* b1    = (const float*)d_in[6];
    const float* W2w   = (const float*)d_in[7];
    const float* b2    = (const float*)d_in[8];
    const float* fcW   = (const float*)d_in[9];
    const float* fcb   = (const float*)d_in[10];
    const float* gamma = (const float*)d_in[11];
    const float* beta  = (const float*)d_in[12];
    const float* q     = (const float*)d_in[13];
    float* out = (float*)d_out;

    zero_kernel<<<(Nn + 1023) / 1024, 1024>>>();                 // launch 1
    prep<<<NBLK1, 256>>>(src, dst, feats);                       // launch 2
    spmm<<<(Nn + 7) / 8, 256>>>(0, 0, 1);                        // launch 3
    spmm<<<(Nn + 7) / 8, 256>>>(1, 1, 1);                        // launch 4 <- ncu window
    spmm<<<(Nn + 7) / 8, 256>>>(0, 2, 0);                        // launch 5
    gmatb<<<128, 256>>>(fcW, W0, W1, W2w, fcb, b0, b1, b2);      // launch 6
    stats_mma<<<STATS_BLOCKS, 384>>>();                          // launch 7
    reduce_stats<<<(C3 * C3 + 255) / 256, 256>>>();              // launch 8
    bnprep<<<128, 192>>>(gamma, beta);                           // launch 9
    w2c0<<<(C3 * Dd + 255) / 256, 256>>>(q);                     // launch 10
    out_mma<<<(Nn + 63) / 64, 256>>>(out);                       // launch 11
}

// round 7
// speedup vs baseline: 2.1182x; 1.0117x over previous
#include <cuda_runtime.h>
#include <cstdint>

#define Nn   100000
#define Ee   1600000
#define Dd   64
#define HIDv 512
#define C3   192
#define NBLK1 ((Nn + 255) / 256)   // 391
#define STATS_BLOCKS 148
#define GM_BLOCKS 128
#define KT 32
#define PADS 36

// ---------------- device scratch ----------------
__device__ __align__(16) float g_ua[Nn * Dd];
__device__ __align__(16) float g_ub[Nn * Dd];
__device__ __align__(16) float g_H[(size_t)Nn * C3];
__device__ float g_norm[Nn];
__device__ float g_norm2[Nn];
__device__ int   g_deg[Nn];
__device__ int   g_rowptr[Nn + 1];
__device__ int   g_cursor[Nn];
__device__ int   g_csr[Ee];
__device__ int   g_bsum[512];
__device__ int   g_barcnt[8];
__device__ __align__(16) float g_G[HIDv * C3];
__device__ float g_bterm[HIDv];
__device__ __align__(16) float g_Cpart[(size_t)STATS_BLOCKS * C3 * C3];
__device__ float g_mHpart[STATS_BLOCKS * C3];
__device__ __align__(16) float g_Cmat[C3 * C3];
__device__ float g_mH[C3];
__device__ float g_scale[HIDv];
__device__ float g_shift[HIDv];
__device__ __align__(16) float g_W2[C3 * Dd];
__device__ __align__(16) float g_c0[Dd];

__device__ __forceinline__ float tf32r(float x) {
    uint32_t u;
    asm("cvt.rna.tf32.f32 %0, %1;" : "=r"(u) : "f"(x));
    return __uint_as_float(u);
}
__device__ __forceinline__ uint32_t f2u(float x) { return __float_as_uint(x); }

__device__ __forceinline__ void mma_tf32(float4& d, uint32_t a0, uint32_t a1, uint32_t a2, uint32_t a3,
                                         uint32_t b0, uint32_t b1) {
    asm volatile(
        "mma.sync.aligned.m16n8k8.row.col.f32.tf32.tf32.f32 "
        "{%0,%1,%2,%3}, {%4,%5,%6,%7}, {%8,%9}, {%0,%1,%2,%3};"
        : "+f"(d.x), "+f"(d.y), "+f"(d.z), "+f"(d.w)
        : "r"(a0), "r"(a1), "r"(a2), "r"(a3), "r"(b0), "r"(b1));
}

// software global barrier; all `target` blocks co-resident
__device__ __forceinline__ void gbarN(int k, int target) {
    __syncthreads();
    if (threadIdx.x == 0) {
        __threadfence();
        atomicAdd(&g_barcnt[k], 1);
        while (*(volatile int*)&g_barcnt[k] < target) { }
        __threadfence();
    }
    __syncthreads();
}

__device__ __forceinline__ void hillis256(int* sh, int t) {
#pragma unroll
    for (int off = 1; off < 256; off <<= 1) {
        int x = (t >= off) ? sh[t - off] : 0;
        __syncthreads();
        sh[t] += x;
        __syncthreads();
    }
}

// ---------------- kernel 1: fused zero + count + scan + norm + scale + csr ----------------
__global__ __launch_bounds__(256) void prep(const int* __restrict__ src,
                                            const int* __restrict__ dst,
                                            const float* __restrict__ feats) {
    __shared__ int sh[256];
    __shared__ float snorm[256];
    int b = blockIdx.x, t = threadIdx.x;
    int i = b * 256 + t;

    // phase Z: zero degree array
    for (int idx = i; idx < Nn; idx += NBLK1 * 256) g_deg[idx] = 0;
    gbarN(0, NBLK1);

    // phase A0: degree histogram
    for (int e = i; e < Ee; e += NBLK1 * 256)
        atomicAdd(&g_deg[dst[e]], 1);
    gbarN(1, NBLK1);

    // phase A: block-local exclusive scan of degrees
    int v = (i < Nn) ? g_deg[i] : 0;
    sh[t] = v;
    __syncthreads();
    hillis256(sh, t);
    int excl = sh[t] - v;
    if (t == 255) g_bsum[b] = sh[255];
    gbarN(2, NBLK1);

    // phase B: block 0 scans the 391 block sums
    if (b == 0) {
        int v1 = *(volatile int*)&g_bsum[t];
        sh[t] = v1;
        __syncthreads();
        hillis256(sh, t);
        int s1 = sh[t];
        int tot1 = sh[255];
        __syncthreads();
        int v2 = (t + 256 < NBLK1) ? *(volatile int*)&g_bsum[t + 256] : 0;
        sh[t] = v2;
        __syncthreads();
        hillis256(sh, t);
        int s2 = sh[t] + tot1;
        __syncthreads();
        g_bsum[t] = s1 - v1;
        if (t + 256 < NBLK1) g_bsum[t + 256] = s2 - v2;
    }
    gbarN(3, NBLK1);

    // phase C: finalize rowptr/cursor/norm, scale features
    int boff = *(volatile int*)&g_bsum[b];
    float nm = 0.f;
    if (i < Nn) {
        int r = excl + boff;
        g_rowptr[i] = r;
        g_cursor[i] = r;
        float f = (v < 1) ? 1.0f : (float)v;
        nm = rsqrtf(f);
        g_norm[i] = nm;
        g_norm2[i] = nm * nm;
        if (i == Nn - 1) g_rowptr[Nn] = Ee;
    }
    snorm[t] = nm;
    __syncthreads();
    int base = b * 256;
    int nnode = min(256, Nn - base);
    if (nnode > 0) {
        const float4* f4 = (const float4*)feats;
        float4* u4 = (float4*)g_ua;
        for (int idx = t; idx < nnode * 16; idx += 256) {
            float4 vv = f4[(size_t)base * 16 + idx];
            float s = snorm[idx >> 4];
            vv.x *= s; vv.y *= s; vv.z *= s; vv.w *= s;
            u4[(size_t)base * 16 + idx] = vv;
        }
    }
    gbarN(4, NBLK1);

    // phase D: CSR fill
    for (int e = i; e < Ee; e += NBLK1 * 256) {
        int d = dst[e];
        int p = atomicAdd(&g_cursor[d], 1);
        g_csr[p] = src[e];
    }
}

// ---------------- SpMM: warp/node, 16 edges per iter (8 float4 gathers in flight) ----------------
__global__ __launch_bounds__(256) void spmm(int srcbuf, int jcol, int writeU) {
    int node = blockIdx.x * 8 + (threadIdx.x >> 5);
    if (node >= Nn) return;
    int lane = threadIdx.x & 31;
    int q = lane & 15, half = lane >> 4;
    const float4* __restrict__ uin = (const float4*)(srcbuf ? g_ub : g_ua);
    float4* __restrict__ uout = (float4*)(srcbuf ? g_ua : g_ub);
    int beg = g_rowptr[node];
    int end = g_rowptr[node + 1];
    float4 accA = make_float4(0.f, 0.f, 0.f, 0.f);
    float4 accB = make_float4(0.f, 0.f, 0.f, 0.f);
    int i = beg;
    // main: 16 edges/iter. one coalesced csr load + 8 independent float4 gathers
    for (; i + 16 <= end; i += 16) {
        int cv = g_csr[i + (lane & 15)];
        int s[8];
#pragma unroll
        for (int e = 0; e < 8; e++) s[e] = __shfl_sync(0xffffffffu, cv, 2 * e + half);
        float4 v[8];
#pragma unroll
        for (int e = 0; e < 8; e++) v[e] = uin[s[e] * 16 + q];
#pragma unroll
        for (int e = 0; e < 4; e++) {
            accA.x += v[e].x; accA.y += v[e].y; accA.z += v[e].z; accA.w += v[e].w;
        }
#pragma unroll
        for (int e = 4; e < 8; e++) {
            accB.x += v[e].x; accB.y += v[e].y; accB.z += v[e].z; accB.w += v[e].w;
        }
    }
    // 8-edge step
    if (i + 8 <= end) {
        int cv = g_csr[i + (lane & 7)];
        int s0 = __shfl_sync(0xffffffffu, cv, half);
        int s1 = __shfl_sync(0xffffffffu, cv, 2 + half);
        int s2 = __shfl_sync(0xffffffffu, cv, 4 + half);
        int s3 = __shfl_sync(0xffffffffu, cv, 6 + half);
        float4 v0 = uin[s0 * 16 + q];
        float4 v1 = uin[s1 * 16 + q];
        float4 v2 = uin[s2 * 16 + q];
        float4 v3 = uin[s3 * 16 + q];
        accA.x += v0.x + v1.x; accA.y += v0.y + v1.y;
        accA.z += v0.z + v1.z; accA.w += v0.w + v1.w;
        accB.x += v2.x + v3.x; accB.y += v2.y + v3.y;
        accB.z += v2.z + v3.z; accB.w += v2.w + v3.w;
        i += 8;
    }
    // 2-edge tail
    for (; i < end; i += 2) {
        int e = i + half;
        if (e < end) {
            int s = g_csr[e];
            float4 v = uin[s * 16 + q];
            accA.x += v.x; accA.y += v.y; accA.z += v.z; accA.w += v.w;
        }
    }
    accA.x += accB.x; accA.y += accB.y; accA.z += accB.z; accA.w += accB.w;
    accA.x += __shfl_xor_sync(0xffffffffu, accA.x, 16);
    accA.y += __shfl_xor_sync(0xffffffffu, accA.y, 16);
    accA.z += __shfl_xor_sync(0xffffffffu, accA.z, 16);
    accA.w += __shfl_xor_sync(0xffffffffu, accA.w, 16);
    if (half == 0) {
        float nm = g_norm[node];
        float4 h;
        h.x = tf32r(accA.x * nm); h.y = tf32r(accA.y * nm);
        h.z = tf32r(accA.z * nm); h.w = tf32r(accA.w * nm);
        ((float4*)g_H)[(size_t)node * 48 + jcol * 16 + q] = h;
        if (writeU) {
            float n2 = g_norm2[node];
            float4 u;
            u.x = accA.x * n2; u.y = accA.y * n2;
            u.z = accA.z * n2; u.w = accA.w * n2;
            uout[node * 16 + q] = u;
        }
    }
}

// ---------------- combined: blocks [0,128) gmat+bterm, [128,276) stats via tf32 mma ----------------
union ShGS {
    struct { float Hs[C3 * PADS]; float mred[384]; } st;
    struct { float fw[4 * 1536]; float red[384]; } gm;
};

__global__ __launch_bounds__(384, 1) void gstats(const float* __restrict__ fcW,
                                                 const float* __restrict__ w0,
                                                 const float* __restrict__ w1,
                                                 const float* __restrict__ w2,
                                                 const float* __restrict__ fcb,
                                                 const float* __restrict__ b0,
                                                 const float* __restrict__ b1,
                                                 const float* __restrict__ b2) {
    __shared__ ShGS sh;
    int tid = threadIdx.x;

    if (blockIdx.x < GM_BLOCKS) {
        // ---- gmat + bterm for 4 h-rows ----
        float* fw = sh.gm.fw;
        float* red = sh.gm.red;
        int hb = blockIdx.x * 4;
        for (int i = tid; i < 4 * 1536; i += 384)
            fw[i] = fcW[(size_t)hb * 1536 + i];
        __syncthreads();
        for (int i = tid; i < 4 * 192; i += 384) {
            int hl = i / 192, c = i % 192, j = c >> 6, d = c & 63;
            const float* W = (j == 0) ? w0 : (j == 1) ? w1 : w2;
            const float* f = fw + hl * 1536 + j * 512;
            float acc = 0.f;
#pragma unroll 8
            for (int m = 0; m < 512; m++) acc = fmaf(f[m], W[m * 64 + d], acc);
            g_G[(hb + hl) * C3 + c] = acc;
        }
        for (int r = 0; r < 4; r++) {
            float p = 0.f;
            for (int m = tid; m < 1536; m += 384) {
                float bv = (m < 512) ? b0[m] : (m < 1024) ? b1[m - 512] : b2[m - 1024];
                p = fmaf(fw[r * 1536 + m], bv, p);
            }
            red[tid] = p;
            __syncthreads();
            if (tid < 128) red[tid] += red[tid + 128] + red[tid + 256];
            __syncthreads();
            for (int s = 64; s > 0; s >>= 1) {
                if (tid < s) red[tid] += red[tid + s];
                __syncthreads();
            }
            if (tid == 0) g_bterm[hb + r] = red[0] + fcb[hb + r];
            __syncthreads();
        }
        return;
    }

    // ---- stats ----
    int sb = blockIdx.x - GM_BLOCKS;   // 0..147
    float* Hs = sh.st.Hs;
    float* mred = sh.st.mred;
    int warp = tid >> 5, lane = tid & 31;
    int mg = warp >> 1, ng = warp & 1;
    int lr = lane >> 2, lc = lane & 3;

    float4 acc[2][12];
#pragma unroll
    for (int a = 0; a < 2; a++)
#pragma unroll
        for (int b = 0; b < 12; b++) acc[a][b] = make_float4(0.f, 0.f, 0.f, 0.f);
    float msum = 0.f;

    int cfix = tid % C3;
    int rbase = tid / C3;

    const int ntiles = Nn / KT;
    for (int tile = sb; tile < ntiles; tile += STATS_BLOCKS) {
        int r0 = tile * KT;
        __syncthreads();
#pragma unroll
        for (int i = 0; i < KT / 2; i++) {
            int r = rbase + 2 * i;
            float v = g_H[(size_t)(r0 + r) * C3 + cfix];
            Hs[cfix * PADS + r] = v;
            msum += v;
        }
        __syncthreads();
#pragma unroll
        for (int ks = 0; ks < KT / 8; ks++) {
            int k0 = ks * 8;
            uint32_t a[2][4];
#pragma unroll
            for (int mt = 0; mt < 2; mt++) {
                int m = mg * 32 + mt * 16;
                a[mt][0] = f2u(Hs[(m + lr) * PADS + k0 + lc]);
                a[mt][1] = f2u(Hs[(m + 8 + lr) * PADS + k0 + lc]);
                a[mt][2] = f2u(Hs[(m + lr) * PADS + k0 + lc + 4]);
                a[mt][3] = f2u(Hs[(m + 8 + lr) * PADS + k0 + lc + 4]);
            }
#pragma unroll
            for (int nt = 0; nt < 12; nt++) {
                int n = ng * 96 + nt * 8;
                uint32_t b0v = f2u(Hs[(n + lr) * PADS + k0 + lc]);
                uint32_t b1v = f2u(Hs[(n + lr) * PADS + k0 + lc + 4]);
                mma_tf32(acc[0][nt], a[0][0], a[0][1], a[0][2], a[0][3], b0v, b1v);
                mma_tf32(acc[1][nt], a[1][0], a[1][1], a[1][2], a[1][3], b0v, b1v);
            }
        }
    }

    float* cp = g_Cpart + (size_t)sb * (C3 * C3);
#pragma unroll
    for (int mt = 0; mt < 2; mt++)
#pragma unroll
        for (int nt = 0; nt < 12; nt++) {
            int row = mg * 32 + mt * 16 + lr;
            int col = ng * 96 + nt * 8 + 2 * lc;
            float4 v = acc[mt][nt];
            *(float2*)&cp[(size_t)row * C3 + col] = make_float2(v.x, v.y);
            *(float2*)&cp[(size_t)(row + 8) * C3 + col] = make_float2(v.z, v.w);
        }
    mred[tid] = msum;
    __syncthreads();
    if (tid < C3) g_mHpart[sb * C3 + tid] = mred[tid] + mred[tid + C3];
}

// ---------------- fused: reduce_stats -> bnprep -> w2c0 (persistent 128 blocks) ----------------
__global__ __launch_bounds__(192) void postk(const float* __restrict__ gamma,
                                             const float* __restrict__ beta,
                                             const float* __restrict__ q) {
    int b = blockIdx.x, c = threadIdx.x;
    int gt = b * 192 + c;   // 0..24575
    const float invN = 1.0f / (float)Nn;

    // phase 1: reduce partials
    for (int idx = gt; idx < C3 * C3; idx += GM_BLOCKS * 192) {
        float s = 0.f;
        for (int p = 0; p < STATS_BLOCKS; p++) s += g_Cpart[(size_t)p * (C3 * C3) + idx];
        g_Cmat[idx] = s * invN;
    }
    if (b == 0) {
        float s = 0.f;
        for (int p = 0; p < STATS_BLOCKS; p++) s += g_mHpart[p * C3 + c];
        g_mH[c] = s * invN;
    }
    gbarN(5, GM_BLOCKS);

    // phase 2: bnprep, 4 h per block
    {
        __shared__ float gsh[4][C3];
        __shared__ float red[C3], red2[C3];
        int hb = b * 4;
#pragma unroll
        for (int j = 0; j < 4; j++) gsh[j][c] = g_G[(hb + j) * C3 + c];
        __syncthreads();
        float t0 = 0.f, t1 = 0.f, t2 = 0.f, t3 = 0.f;
        for (int cc = 0; cc < C3; cc++) {
            float cm = g_Cmat[cc * C3 + c];
            t0 = fmaf(cm, gsh[0][cc], t0);
            t1 = fmaf(cm, gsh[1][cc], t1);
            t2 = fmaf(cm, gsh[2][cc], t2);
            t3 = fmaf(cm, gsh[3][cc], t3);
        }
        float mh = g_mH[c];
        float ts[4] = {t0, t1, t2, t3};
#pragma unroll
        for (int j = 0; j < 4; j++) {
            __syncthreads();
            red[c]  = gsh[j][c] * ts[j];
            red2[c] = gsh[j][c] * mh;
            __syncthreads();
            if (c < 64) {
                red[c]  += red[c + 64]  + red[c + 128];
                red2[c] += red2[c + 64] + red2[c + 128];
            }
            __syncthreads();
            for (int s = 32; s > 0; s >>= 1) {
                if (c < s) { red[c] += red[c + s]; red2[c] += red2[c + s]; }
                __syncthreads();
            }
            if (c == 0) {
                int h = hb + j;
                float quad = red[0], dot1 = red2[0], bt = g_bterm[h];
                float mu  = dot1 + bt;
                float ef2 = quad + 2.f * bt * dot1 + bt * bt;
                float var = ef2 - mu * mu;
                float sc  = rsqrtf(var + 1e-5f) * gamma[h];
                g_scale[h] = sc;
                g_shift[h] = beta[h] - mu * sc;
            }
        }
    }
    gbarN(6, GM_BLOCKS);

    // phase 3: w2c0
    if (gt < C3 * Dd) {
        int o = gt & 63, cc = gt >> 6;
        float s = 0.f;
#pragma unroll
        for (int k = 0; k < 8; k++) {
            int h = k * 64 + o;
            s += q[k] * g_scale[h] * g_G[h * C3 + cc];
        }
        g_W2[cc * Dd + o] = tf32r(s);
    }
    if (gt < Dd) {
        float s = 0.f;
#pragma unroll
        for (int k = 0; k < 8; k++) {
            int h = k * 64 + gt;
            s += q[k] * (g_scale[h] * g_bterm[h] + g_shift[h]);
        }
        g_c0[gt] = s;
    }
}

// ---------------- out = H (Nx192) @ W2^T via tf32 mma ----------------
#define PH 68
#define PW 72
__global__ __launch_bounds__(256) void out_mma(float* __restrict__ out) {
    // reset soft-barrier counters for the next replay
    if (blockIdx.x == 0 && threadIdx.x < 8) g_barcnt[threadIdx.x] = 0;

    __shared__ float Hs[64 * PH];
    __shared__ float W2s[64 * PW];
    int tid = threadIdx.x;
    int warp = tid >> 5, lane = tid & 31;
    int mg = warp >> 1, ng = warp & 1;
    int lr = lane >> 2, lc = lane & 3;
    int r0 = blockIdx.x * 64;
    int nr = min(64, Nn - r0);

    float4 acc[4];
#pragma unroll
    for (int a = 0; a < 4; a++) acc[a] = make_float4(0.f, 0.f, 0.f, 0.f);

#pragma unroll
    for (int kc = 0; kc < 3; kc++) {
        __syncthreads();
#pragma unroll
        for (int i = 0; i < 4; i++) {
            int idx4 = tid + i * 256;
            int m = idx4 >> 4, k4 = (idx4 & 15) << 2;
            float4 v = make_float4(0.f, 0.f, 0.f, 0.f);
            if (m < nr) v = *(const float4*)&g_H[(size_t)(r0 + m) * C3 + kc * 64 + k4];
            *(float4*)&Hs[m * PH + k4] = v;
        }
#pragma unroll
        for (int i = 0; i < 4; i++) {
            int idx4 = tid + i * 256;
            int k = idx4 >> 4, n4 = (idx4 & 15) << 2;
            *(float4*)&W2s[k * PW + n4] = *(const float4*)&g_W2[(kc * 64 + k) * Dd + n4];
        }
        __syncthreads();
#pragma unroll
        for (int ks = 0; ks < 8; ks++) {
            int k0 = ks * 8;
            int m0 = mg * 16;
            uint32_t a0 = f2u(Hs[(m0 + lr) * PH + k0 + lc]);
            uint32_t a1 = f2u(Hs[(m0 + 8 + lr) * PH + k0 + lc]);
            uint32_t a2 = f2u(Hs[(m0 + lr) * PH + k0 + lc + 4]);
            uint32_t a3 = f2u(Hs[(m0 + 8 + lr) * PH + k0 + lc + 4]);
#pragma unroll
            for (int nt = 0; nt < 4; nt++) {
                int n0 = ng * 32 + nt * 8;
                uint32_t b0 = f2u(W2s[(k0 + lc) * PW + n0 + lr]);
                uint32_t b1 = f2u(W2s[(k0 + lc + 4) * PW + n0 + lr]);
                mma_tf32(acc[nt], a0, a1, a2, a3, b0, b1);
            }
        }
    }

#pragma unroll
    for (int nt = 0; nt < 4; nt++) {
        int row = mg * 16 + lr;
        int col = ng * 32 + nt * 8 + 2 * lc;
        float2 cc = *(const float2*)&g_c0[col];
        float4 v = acc[nt];
        if (row < nr)
            *(float2*)&out[(size_t)(r0 + row) * Dd + col] = make_float2(v.x + cc.x, v.y + cc.y);
        if (row + 8 < nr)
            *(float2*)&out[(size_t)(r0 + row + 8) * Dd + col] = make_float2(v.z + cc.x, v.w + cc.y);
    }
}

// ---------------- launch ----------------
extern "C" void kernel_launch(void* const* d_in, const int* in_sizes, int n_in,
                              void* d_out, int out_size) {
    const float* feats = (const float*)d_in[0];
    const int*   src   = (const int*)d_in[1];
    const int*   dst   = (const int*)d_in[2];
    const float* W0    = (const float*)d_in[3];
    const float* b0    = (const float*)d_in[4];
    const float* W1    = (const float*)d_in[5];
    const float* b1    = (const float*)d_in[6];
    const float* W2w   = (const float*)d_in[7];
    const float* b2    = (const float*)d_in[8];
    const float* fcW   = (const float*)d_in[9];
    const float* fcb   = (const float*)d_in[10];
    const float* gamma = (const float*)d_in[11];
    const float* beta  = (const float*)d_in[12];
    const float* q     = (const float*)d_in[13];
    float* out = (float*)d_out;

    prep<<<NBLK1, 256>>>(src, dst, feats);                         // launch 1
    spmm<<<(Nn + 7) / 8, 256>>>(0, 0, 1);                          // launch 2
    spmm<<<(Nn + 7) / 8, 256>>>(1, 1, 1);                          // launch 3
    spmm<<<(Nn + 7) / 8, 256>>>(0, 2, 0);                          // launch 4 <- ncu window
    gstats<<<GM_BLOCKS + STATS_BLOCKS, 384>>>(fcW, W0, W1, W2w, fcb, b0, b1, b2); // 5
    postk<<<GM_BLOCKS, 192>>>(gamma, beta, q);                     // launch 6
    out_mma<<<(Nn + 63) / 64, 256>>>(out);                         // launch 7
}